// round 1
// baseline (speedup 1.0000x reference)
#include <cuda_runtime.h>

typedef unsigned long long u64;

__device__ __forceinline__ u64 pk2(float a, float b) {
    u64 r;
    asm("mov.b64 %0, {%1, %2};" : "=l"(r) : "f"(a), "f"(b));
    return r;
}
__device__ __forceinline__ void upk2(u64 v, float &a, float &b) {
    asm("mov.b64 {%0, %1}, %2;" : "=f"(a), "=f"(b) : "l"(v));
}
__device__ __forceinline__ void fma2(u64 &d, u64 a, u64 b) {
    asm("fma.rn.f32x2 %0, %1, %2, %0;" : "+l"(d) : "l"(a), "l"(b));
}

__device__ __forceinline__ float sigm(float v) {
    return __fdividef(1.0f, 1.0f + __expf(-v));
}
__device__ __forceinline__ float tanh_fast(float v) {
    float e = __expf(2.0f * v);
    return 1.0f - __fdividef(2.0f, e + 1.0f);
}

#define TPB 256
#define IN_DIM 16
#define HID 32
#define KDIM 48   // IN_DIM + HID
#define OUT_DIM 8

__global__ __launch_bounds__(TPB) void rgcn_fused_kernel(
    const float* __restrict__ x, const float* __restrict__ h,
    const float* __restrict__ wz, const float* __restrict__ bz,
    const float* __restrict__ wr, const float* __restrict__ br,
    const float* __restrict__ wh, const float* __restrict__ bh,
    const float* __restrict__ wl, const float* __restrict__ bl,
    float* __restrict__ out, float* __restrict__ hnew, int N)
{
    // Combined (w[0]+w[1]) weights, row-major [K=48][HID=32]
    __shared__ float sWz[KDIM * HID];
    __shared__ float sWr[KDIM * HID];
    __shared__ float sWh[KDIM * HID];
    __shared__ float sWl[HID * OUT_DIM];
    __shared__ float sB[3 * HID + OUT_DIM];  // bz | br | bh | bl

    for (int t = threadIdx.x; t < KDIM * HID; t += TPB) {
        sWz[t] = wz[t] + wz[t + KDIM * HID];
        sWr[t] = wr[t] + wr[t + KDIM * HID];
        sWh[t] = wh[t] + wh[t + KDIM * HID];
    }
    for (int t = threadIdx.x; t < HID * OUT_DIM; t += TPB) sWl[t] = wl[t];
    if (threadIdx.x < HID) {
        sB[threadIdx.x]           = bz[threadIdx.x];
        sB[HID + threadIdx.x]     = br[threadIdx.x];
        sB[2 * HID + threadIdx.x] = bh[threadIdx.x];
    }
    if (threadIdx.x < OUT_DIM) sB[3 * HID + threadIdx.x] = bl[threadIdx.x];
    __syncthreads();

    int i = blockIdx.x * TPB + threadIdx.x;
    if (i >= N) return;

    // ---- Load xh = [x_i (16) | h_i (32)] into registers ----
    float xh[KDIM];
    {
        const float4* x4 = reinterpret_cast<const float4*>(x) + (size_t)i * (IN_DIM / 4);
        #pragma unroll
        for (int q = 0; q < IN_DIM / 4; q++) {
            float4 v = x4[q];
            xh[4 * q + 0] = v.x; xh[4 * q + 1] = v.y;
            xh[4 * q + 2] = v.z; xh[4 * q + 3] = v.w;
        }
        const float4* h4 = reinterpret_cast<const float4*>(h) + (size_t)i * (HID / 4);
        #pragma unroll
        for (int q = 0; q < HID / 4; q++) {
            float4 v = h4[q];
            xh[IN_DIM + 4 * q + 0] = v.x; xh[IN_DIM + 4 * q + 1] = v.y;
            xh[IN_DIM + 4 * q + 2] = v.z; xh[IN_DIM + 4 * q + 3] = v.w;
        }
    }

    // ---- z and r pre-activations (shared k loop, one a2 pack per k) ----
    u64 accz[HID / 2], accr[HID / 2];
    #pragma unroll
    for (int p = 0; p < HID / 2; p++) {
        accz[p] = pk2(sB[2 * p], sB[2 * p + 1]);
        accr[p] = pk2(sB[HID + 2 * p], sB[HID + 2 * p + 1]);
    }
    #pragma unroll
    for (int k = 0; k < KDIM; k++) {
        u64 a2 = pk2(xh[k], xh[k]);
        const float4* z4 = reinterpret_cast<const float4*>(sWz + k * HID);
        const float4* r4 = reinterpret_cast<const float4*>(sWr + k * HID);
        #pragma unroll
        for (int q = 0; q < HID / 4; q++) {
            float4 wv = z4[q];
            fma2(accz[2 * q + 0], a2, pk2(wv.x, wv.y));
            fma2(accz[2 * q + 1], a2, pk2(wv.z, wv.w));
            float4 rv = r4[q];
            fma2(accr[2 * q + 0], a2, pk2(rv.x, rv.y));
            fma2(accr[2 * q + 1], a2, pk2(rv.z, rv.w));
        }
    }

    // ---- activations: z = sigmoid, hr = h * sigmoid(r) (keep h in xh) ----
    float zg[HID];
    float hr[HID];
    #pragma unroll
    for (int p = 0; p < HID / 2; p++) {
        float a, b;
        upk2(accz[p], a, b);
        zg[2 * p + 0] = sigm(a);
        zg[2 * p + 1] = sigm(b);
        float c, d;
        upk2(accr[p], c, d);
        hr[2 * p + 0] = xh[IN_DIM + 2 * p + 0] * sigm(c);
        hr[2 * p + 1] = xh[IN_DIM + 2 * p + 1] * sigm(d);
    }

    // ---- h_tilde pre-activation over xhr = [x | h*r] ----
    u64 acch[HID / 2];
    #pragma unroll
    for (int p = 0; p < HID / 2; p++)
        acch[p] = pk2(sB[2 * HID + 2 * p], sB[2 * HID + 2 * p + 1]);
    #pragma unroll
    for (int k = 0; k < KDIM; k++) {
        float a = (k < IN_DIM) ? xh[k] : hr[k - IN_DIM];
        u64 a2 = pk2(a, a);
        const float4* w4 = reinterpret_cast<const float4*>(sWh + k * HID);
        #pragma unroll
        for (int q = 0; q < HID / 4; q++) {
            float4 wv = w4[q];
            fma2(acch[2 * q + 0], a2, pk2(wv.x, wv.y));
            fma2(acch[2 * q + 1], a2, pk2(wv.z, wv.w));
        }
    }

    // ---- h_new = z*h + (1-z)*tanh(acch) ----
    float hn[HID];
    #pragma unroll
    for (int p = 0; p < HID / 2; p++) {
        float a, b;
        upk2(acch[p], a, b);
        float t0 = tanh_fast(a);
        float t1 = tanh_fast(b);
        int j0 = 2 * p, j1 = 2 * p + 1;
        hn[j0] = zg[j0] * xh[IN_DIM + j0] + (1.0f - zg[j0]) * t0;
        hn[j1] = zg[j1] * xh[IN_DIM + j1] + (1.0f - zg[j1]) * t1;
    }

    // ---- out = relu(h_new) @ w_lin + b_lin ----
    u64 acco[OUT_DIM / 2];
    #pragma unroll
    for (int p = 0; p < OUT_DIM / 2; p++)
        acco[p] = pk2(sB[3 * HID + 2 * p], sB[3 * HID + 2 * p + 1]);
    #pragma unroll
    for (int k = 0; k < HID; k++) {
        float a = fmaxf(hn[k], 0.0f);
        u64 a2 = pk2(a, a);
        const float4* w4 = reinterpret_cast<const float4*>(sWl + k * OUT_DIM);
        #pragma unroll
        for (int q = 0; q < OUT_DIM / 4; q++) {
            float4 wv = w4[q];
            fma2(acco[2 * q + 0], a2, pk2(wv.x, wv.y));
            fma2(acco[2 * q + 1], a2, pk2(wv.z, wv.w));
        }
    }

    // ---- stores (vectorized) ----
    {
        float o[OUT_DIM];
        #pragma unroll
        for (int p = 0; p < OUT_DIM / 2; p++) upk2(acco[p], o[2 * p], o[2 * p + 1]);
        float4* o4 = reinterpret_cast<float4*>(out) + (size_t)i * (OUT_DIM / 4);
        o4[0] = make_float4(o[0], o[1], o[2], o[3]);
        o4[1] = make_float4(o[4], o[5], o[6], o[7]);

        float4* hn4 = reinterpret_cast<float4*>(hnew) + (size_t)i * (HID / 4);
        #pragma unroll
        for (int q = 0; q < HID / 4; q++)
            hn4[q] = make_float4(hn[4 * q], hn[4 * q + 1], hn[4 * q + 2], hn[4 * q + 3]);
    }
}

extern "C" void kernel_launch(void* const* d_in, const int* in_sizes, int n_in,
                              void* d_out, int out_size) {
    // metadata order: x, edge_index, edge_weight, h, w_z, b_z, w_r, b_r,
    //                 w_h, b_h, w_lin, b_lin
    const float* x  = (const float*)d_in[0];
    const float* h  = (const float*)d_in[3];
    const float* wz = (const float*)d_in[4];
    const float* bz = (const float*)d_in[5];
    const float* wr = (const float*)d_in[6];
    const float* br = (const float*)d_in[7];
    const float* wh = (const float*)d_in[8];
    const float* bh = (const float*)d_in[9];
    const float* wl = (const float*)d_in[10];
    const float* bl = (const float*)d_in[11];

    int N = in_sizes[0] / IN_DIM;

    // Output tuple (out, h_new) flattened in order: [N*8] then [N*32]
    float* out  = (float*)d_out;
    float* hnew = out + (size_t)N * OUT_DIM;

    int grid = (N + TPB - 1) / TPB;
    rgcn_fused_kernel<<<grid, TPB>>>(x, h, wz, bz, wr, br, wh, bh, wl, bl,
                                     out, hnew, N);
}

// round 3
// speedup vs baseline: 2.3171x; 2.3171x over previous
#include <cuda_runtime.h>
#include <cuda_bf16.h>
#include <cstdint>

typedef uint32_t u32;

#define IN_DIM 16
#define HID 32
#define KD 48
#define OUT_DIM 8
#define TPB 128
#define TILE_M 128
#define STRD 28   /* u32 stride of staging rows: 28r mod 32 = 4-spaced -> conflict-free frag reads */

/* ------------- fragment-ordered, pre-split weight tables ------------- */
/* B_zr: [kt 0..2][nt 0..7][lane] ; B_h: [kt 0..2][nt 0..3][lane] ; B_l: [kt 0..1][lane] */
__device__ uint2 gBzr_h[768], gBzr_l[768];
__device__ uint2 gBh_h[384],  gBh_l[384];
__device__ uint2 gBl_h[64],   gBl_l[64];

__device__ __forceinline__ void split2(float a, float b, u32 &hi, u32 &lo) {
    __nv_bfloat16 ha = __float2bfloat16_rn(a), hb = __float2bfloat16_rn(b);
    __nv_bfloat16 la = __float2bfloat16_rn(a - __bfloat162float(ha));
    __nv_bfloat16 lb = __float2bfloat16_rn(b - __bfloat162float(hb));
    __nv_bfloat162 H; H.x = ha; H.y = hb;
    __nv_bfloat162 L; L.x = la; L.y = lb;
    hi = *reinterpret_cast<u32*>(&H);
    lo = *reinterpret_cast<u32*>(&L);
}
__device__ __forceinline__ float2 bf2f(u32 v) {
    __nv_bfloat162 t = *reinterpret_cast<__nv_bfloat162*>(&v);
    return make_float2(__bfloat162float(t.x), __bfloat162float(t.y));
}
__device__ __forceinline__ float sigm(float v) {
    return __fdividef(1.0f, 1.0f + __expf(-v));
}
__device__ __forceinline__ float tanh_fast(float v) {
    float e = __expf(2.0f * v);
    return 1.0f - __fdividef(2.0f, e + 1.0f);
}

/* ---- mma.sync m16n8k16 bf16 (sm_80+, no 'a' feature needed) ---- */
__device__ __forceinline__ void mma16816(float c[4], const u32 a[4], uint2 b) {
    asm volatile(
        "mma.sync.aligned.m16n8k16.row.col.f32.bf16.bf16.f32 "
        "{%0,%1,%2,%3}, {%4,%5,%6,%7}, {%8,%9}, {%0,%1,%2,%3};"
        : "+f"(c[0]), "+f"(c[1]), "+f"(c[2]), "+f"(c[3])
        : "r"(a[0]), "r"(a[1]), "r"(a[2]), "r"(a[3]), "r"(b.x), "r"(b.y));
}

/* ================= prep: fold w0+w1, split, emit lane-ordered fragments ==== */
__global__ void rgcn_prep(const float* __restrict__ wz, const float* __restrict__ wr,
                          const float* __restrict__ wh, const float* __restrict__ wl) {
    int idx = blockIdx.x * blockDim.x + threadIdx.x;
    if (idx >= 38 * 32) return;
    int lane = idx & 31, fid = idx >> 5;
    int gid = lane >> 2, ctg = lane & 3;

    int kt, nt, which;
    uint2* dsth; uint2* dstl; int slot;
    if (fid < 24)      { kt = fid >> 3; nt = fid & 7;        which = 0; dsth = gBzr_h; dstl = gBzr_l; slot = fid * 32 + lane; }
    else if (fid < 36) { int f = fid - 24; kt = f >> 2; nt = f & 3; which = 1; dsth = gBh_h; dstl = gBh_l; slot = f * 32 + lane; }
    else               { kt = fid - 36; nt = 0;              which = 2; dsth = gBl_h;  dstl = gBl_l;  slot = kt * 32 + lane; }

    int n = nt * 8 + gid;
    float v[4];
    #pragma unroll
    for (int p = 0; p < 4; p++) {
        int k = kt * 16 + ctg * 2 + (p & 1) + ((p >> 1) * 8);
        float val;
        if (which == 0) {
            if (n < 32) val = wz[k * 32 + n] + wz[1536 + k * 32 + n];
            else        val = wr[k * 32 + (n - 32)] + wr[1536 + k * 32 + (n - 32)];
        } else if (which == 1) {
            val = wh[k * 32 + n] + wh[1536 + k * 32 + n];
        } else {
            val = wl[k * 8 + n];
        }
        v[p] = val;
    }
    uint2 hi, lo;
    split2(v[0], v[1], hi.x, lo.x);
    split2(v[2], v[3], hi.y, lo.y);
    dsth[slot] = hi;
    dstl[slot] = lo;
}

/* ================= main fused kernel (warp-local, no CTA syncs) ============ */
__global__ void __launch_bounds__(TPB) rgcn_mma_kernel(
    const float* __restrict__ x, const float* __restrict__ h,
    const float* __restrict__ bz, const float* __restrict__ br,
    const float* __restrict__ bh, const float* __restrict__ bl,
    float* __restrict__ out, float* __restrict__ hnew, int N)
{
    __shared__ u32 sA_h[TILE_M * STRD];
    __shared__ u32 sA_l[TILE_M * STRD];

    const int tid = threadIdx.x;
    const int lane = tid & 31;
    const int warp = tid >> 5;
    const int gid = lane >> 2, ctg = lane & 3;
    const int nodeBase = blockIdx.x * TILE_M;
    const int node = nodeBase + tid;

    /* ---- stage A = [x | h] bf16 hi/lo into this thread's row ---- */
    {
        float v[KD];
        if (node < N) {
            const float4* x4 = reinterpret_cast<const float4*>(x) + (size_t)node * 4;
            #pragma unroll
            for (int q = 0; q < 4; q++) {
                float4 t = x4[q];
                v[4 * q] = t.x; v[4 * q + 1] = t.y; v[4 * q + 2] = t.z; v[4 * q + 3] = t.w;
            }
            const float4* h4 = reinterpret_cast<const float4*>(h) + (size_t)node * 8;
            #pragma unroll
            for (int q = 0; q < 8; q++) {
                float4 t = h4[q];
                v[IN_DIM + 4 * q] = t.x; v[IN_DIM + 4 * q + 1] = t.y;
                v[IN_DIM + 4 * q + 2] = t.z; v[IN_DIM + 4 * q + 3] = t.w;
            }
        } else {
            #pragma unroll
            for (int q = 0; q < KD; q++) v[q] = 0.0f;
        }
        u32 ph[24], pl[24];
        #pragma unroll
        for (int c = 0; c < 24; c++) split2(v[2 * c], v[2 * c + 1], ph[c], pl[c]);
        uint4* dh = reinterpret_cast<uint4*>(sA_h + tid * STRD);
        uint4* dl = reinterpret_cast<uint4*>(sA_l + tid * STRD);
        #pragma unroll
        for (int q = 0; q < 6; q++) {
            dh[q] = make_uint4(ph[4 * q], ph[4 * q + 1], ph[4 * q + 2], ph[4 * q + 3]);
            dl[q] = make_uint4(pl[4 * q], pl[4 * q + 1], pl[4 * q + 2], pl[4 * q + 3]);
        }
    }
    __syncwarp();

    const u32* rowH = sA_h + warp * 32 * STRD;
    const u32* rowL = sA_l + warp * 32 * STRD;

    auto ld_afrag = [&](const u32* base, int mt, int kt, u32 f[4]) {
        int r = mt * 16 + gid;
        int c = kt * 8 + ctg;
        f[0] = base[r * STRD + c];
        f[1] = base[(r + 8) * STRD + c];
        f[2] = base[r * STRD + c + 4];
        f[3] = base[(r + 8) * STRD + c + 4];
    };

    /* ---- GEMM1: C1[128x64] = A[128x48] @ B_zr (z|r) ---- */
    float c1[2][8][4];
    #pragma unroll
    for (int mt = 0; mt < 2; mt++)
        #pragma unroll
        for (int nt = 0; nt < 8; nt++)
            #pragma unroll
            for (int i = 0; i < 4; i++) c1[mt][nt][i] = 0.0f;

    #pragma unroll
    for (int kt = 0; kt < 3; kt++) {
        u32 ah[2][4], al[2][4];
        #pragma unroll
        for (int mt = 0; mt < 2; mt++) {
            ld_afrag(rowH, mt, kt, ah[mt]);
            ld_afrag(rowL, mt, kt, al[mt]);
        }
        #pragma unroll
        for (int nt = 0; nt < 8; nt++) {
            uint2 Bh = __ldg(&gBzr_h[(kt * 8 + nt) * 32 + lane]);
            uint2 Bl = __ldg(&gBzr_l[(kt * 8 + nt) * 32 + lane]);
            #pragma unroll
            for (int mt = 0; mt < 2; mt++) {
                mma16816(c1[mt][nt], ah[mt], Bh);
                mma16816(c1[mt][nt], al[mt], Bh);
                mma16816(c1[mt][nt], ah[mt], Bl);
            }
        }
    }

    /* ---- epilogue 1: z = sig(c+bz); a2 = h * sig(c+br); restage a2 ---- */
    float2 bzv[4], brv[4];
    const int cbase = ctg * 2;
    #pragma unroll
    for (int nt = 0; nt < 4; nt++) {
        bzv[nt] = make_float2(__ldg(bz + nt * 8 + cbase), __ldg(bz + nt * 8 + cbase + 1));
        brv[nt] = make_float2(__ldg(br + nt * 8 + cbase), __ldg(br + nt * 8 + cbase + 1));
    }

    float hf[2][4][4];  /* h_old at fragment positions */
    #pragma unroll
    for (int mt = 0; mt < 2; mt++)
        #pragma unroll
        for (int nt = 0; nt < 4; nt++) {
            int r = mt * 16 + gid;
            int ix = 8 + nt * 4 + ctg;
            float2 f0 = bf2f(rowH[r * STRD + ix]);
            float2 g0 = bf2f(rowL[r * STRD + ix]);
            hf[mt][nt][0] = f0.x + g0.x; hf[mt][nt][1] = f0.y + g0.y;
            float2 f1 = bf2f(rowH[(r + 8) * STRD + ix]);
            float2 g1 = bf2f(rowL[(r + 8) * STRD + ix]);
            hf[mt][nt][2] = f1.x + g1.x; hf[mt][nt][3] = f1.y + g1.y;
        }
    __syncwarp();

    float zf[2][4][4];
    #pragma unroll
    for (int mt = 0; mt < 2; mt++)
        #pragma unroll
        for (int nt = 0; nt < 4; nt++) {
            float a2v[4];
            #pragma unroll
            for (int i = 0; i < 4; i++) {
                float bzi = (i & 1) ? bzv[nt].y : bzv[nt].x;
                float bri = (i & 1) ? brv[nt].y : brv[nt].x;
                zf[mt][nt][i] = sigm(c1[mt][nt][i] + bzi);
                a2v[i] = hf[mt][nt][i] * sigm(c1[mt][nt + 4][i] + bri);
            }
            int r = mt * 16 + gid;
            int ix = 8 + nt * 4 + ctg;
            u32 hi0, lo0, hi1, lo1;
            split2(a2v[0], a2v[1], hi0, lo0);
            split2(a2v[2], a2v[3], hi1, lo1);
            const_cast<u32*>(rowH)[r * STRD + ix] = hi0;
            const_cast<u32*>(rowL)[r * STRD + ix] = lo0;
            const_cast<u32*>(rowH)[(r + 8) * STRD + ix] = hi1;
            const_cast<u32*>(rowL)[(r + 8) * STRD + ix] = lo1;
        }
    __syncwarp();

    /* ---- GEMM2: C2[128x32] = [x | a2] @ B_h[48x32] ---- */
    float c2[2][4][4];
    #pragma unroll
    for (int mt = 0; mt < 2; mt++)
        #pragma unroll
        for (int nt = 0; nt < 4; nt++)
            #pragma unroll
            for (int i = 0; i < 4; i++) c2[mt][nt][i] = 0.0f;

    #pragma unroll
    for (int kt = 0; kt < 3; kt++) {
        u32 ah[2][4], al[2][4];
        #pragma unroll
        for (int mt = 0; mt < 2; mt++) {
            ld_afrag(rowH, mt, kt, ah[mt]);
            ld_afrag(rowL, mt, kt, al[mt]);
        }
        #pragma unroll
        for (int nt = 0; nt < 4; nt++) {
            uint2 Bh = __ldg(&gBh_h[(kt * 4 + nt) * 32 + lane]);
            uint2 Bl = __ldg(&gBh_l[(kt * 4 + nt) * 32 + lane]);
            #pragma unroll
            for (int mt = 0; mt < 2; mt++) {
                mma16816(c2[mt][nt], ah[mt], Bh);
                mma16816(c2[mt][nt], al[mt], Bh);
                mma16816(c2[mt][nt], ah[mt], Bl);
            }
        }
    }

    /* ---- epilogue 2: hn = z*h + (1-z)*tanh(c2+bh); store; restage relu ---- */
    float2 bhv[4];
    #pragma unroll
    for (int nt = 0; nt < 4; nt++)
        bhv[nt] = make_float2(__ldg(bh + nt * 8 + cbase), __ldg(bh + nt * 8 + cbase + 1));

    __syncwarp();
    #pragma unroll
    for (int mt = 0; mt < 2; mt++)
        #pragma unroll
        for (int nt = 0; nt < 4; nt++) {
            float hn[4];
            #pragma unroll
            for (int i = 0; i < 4; i++) {
                float bhi = (i & 1) ? bhv[nt].y : bhv[nt].x;
                float ht = tanh_fast(c2[mt][nt][i] + bhi);
                float zg = zf[mt][nt][i];
                hn[i] = zg * hf[mt][nt][i] + (1.0f - zg) * ht;
            }
            int r = mt * 16 + gid;
            int n0 = nodeBase + warp * 32 + r;
            if (n0 < N)
                *reinterpret_cast<float2*>(hnew + (size_t)n0 * HID + nt * 8 + cbase) =
                    make_float2(hn[0], hn[1]);
            int n1 = n0 + 8;
            if (n1 < N)
                *reinterpret_cast<float2*>(hnew + (size_t)n1 * HID + nt * 8 + cbase) =
                    make_float2(hn[2], hn[3]);

            /* relu + split into staging cols 0..31 (u32 idx 0..15) */
            u32 hi0, lo0, hi1, lo1;
            split2(fmaxf(hn[0], 0.0f), fmaxf(hn[1], 0.0f), hi0, lo0);
            split2(fmaxf(hn[2], 0.0f), fmaxf(hn[3], 0.0f), hi1, lo1);
            int ix = nt * 4 + ctg;
            const_cast<u32*>(rowH)[r * STRD + ix] = hi0;
            const_cast<u32*>(rowL)[r * STRD + ix] = lo0;
            const_cast<u32*>(rowH)[(r + 8) * STRD + ix] = hi1;
            const_cast<u32*>(rowL)[(r + 8) * STRD + ix] = lo1;
        }
    __syncwarp();

    /* ---- GEMM3: out[128x8] = relu(hn)[128x32] @ wl ---- */
    float co[2][4];
    #pragma unroll
    for (int mt = 0; mt < 2; mt++)
        #pragma unroll
        for (int i = 0; i < 4; i++) co[mt][i] = 0.0f;

    #pragma unroll
    for (int kt = 0; kt < 2; kt++) {
        u32 ah[2][4], al[2][4];
        #pragma unroll
        for (int mt = 0; mt < 2; mt++) {
            ld_afrag(rowH, mt, kt, ah[mt]);
            ld_afrag(rowL, mt, kt, al[mt]);
        }
        uint2 Bh = __ldg(&gBl_h[kt * 32 + lane]);
        uint2 Bl = __ldg(&gBl_l[kt * 32 + lane]);
        #pragma unroll
        for (int mt = 0; mt < 2; mt++) {
            mma16816(co[mt], ah[mt], Bh);
            mma16816(co[mt], al[mt], Bh);
            mma16816(co[mt], ah[mt], Bl);
        }
    }

    float2 blv = make_float2(__ldg(bl + cbase), __ldg(bl + cbase + 1));
    #pragma unroll
    for (int mt = 0; mt < 2; mt++) {
        int r = mt * 16 + gid;
        int n0 = nodeBase + warp * 32 + r;
        if (n0 < N)
            *reinterpret_cast<float2*>(out + (size_t)n0 * OUT_DIM + cbase) =
                make_float2(co[mt][0] + blv.x, co[mt][1] + blv.y);
        int n1 = n0 + 8;
        if (n1 < N)
            *reinterpret_cast<float2*>(out + (size_t)n1 * OUT_DIM + cbase) =
                make_float2(co[mt][2] + blv.x, co[mt][3] + blv.y);
    }
}

extern "C" void kernel_launch(void* const* d_in, const int* in_sizes, int n_in,
                              void* d_out, int out_size) {
    const float* x  = (const float*)d_in[0];
    const float* h  = (const float*)d_in[3];
    const float* wz = (const float*)d_in[4];
    const float* bz = (const float*)d_in[5];
    const float* wr = (const float*)d_in[6];
    const float* br = (const float*)d_in[7];
    const float* wh = (const float*)d_in[8];
    const float* bh = (const float*)d_in[9];
    const float* wl = (const float*)d_in[10];
    const float* bl = (const float*)d_in[11];

    int N = in_sizes[0] / IN_DIM;
    float* out  = (float*)d_out;
    float* hnew = out + (size_t)N * OUT_DIM;

    rgcn_prep<<<5, 256>>>(wz, wr, wh, wl);

    int grid = (N + TILE_M - 1) / TILE_M;
    rgcn_mma_kernel<<<grid, TPB>>>(x, h, bz, br, bh, bl, out, hnew, N);
}

// round 4
// speedup vs baseline: 2.4411x; 1.0535x over previous
#include <cuda_runtime.h>
#include <cuda_bf16.h>
#include <cstdint>

typedef uint32_t u32;

#define IN_DIM 16
#define HID 32
#define OUT_DIM 8
#define TPB 128
#define TILE_M 128

/* ------------- fragment-ordered, pre-split weight tables ------------- */
__device__ uint2 gBzr_h[768], gBzr_l[768];
__device__ uint2 gBh_h[384],  gBh_l[384];
__device__ uint2 gBl_h[64],   gBl_l[64];

/* ---------------- helpers ---------------- */
__device__ __forceinline__ u32 pkbf(float a, float b) {   /* lo=a, hi=b */
    u32 r;
    asm("cvt.rn.bf16x2.f32 %0, %1, %2;" : "=r"(r) : "f"(b), "f"(a));
    return r;
}
__device__ __forceinline__ void splitf2(float a, float b, u32 &hi, u32 &lo) {
    hi = pkbf(a, b);
    float f0 = __uint_as_float(hi << 16);
    float f1 = __uint_as_float(hi & 0xFFFF0000u);
    lo = pkbf(a - f0, b - f1);
}
__device__ __forceinline__ void split2(float a, float b, u32 &hi, u32 &lo) {
    __nv_bfloat16 ha = __float2bfloat16_rn(a), hb = __float2bfloat16_rn(b);
    __nv_bfloat16 la = __float2bfloat16_rn(a - __bfloat162float(ha));
    __nv_bfloat16 lb = __float2bfloat16_rn(b - __bfloat162float(hb));
    __nv_bfloat162 H; H.x = ha; H.y = hb;
    __nv_bfloat162 L; L.x = la; L.y = lb;
    hi = *reinterpret_cast<u32*>(&H);
    lo = *reinterpret_cast<u32*>(&L);
}
__device__ __forceinline__ float sigm(float v) {
    return __fdividef(1.0f, 1.0f + __expf(-v));
}
__device__ __forceinline__ float tanh_fast(float v) {
    float e = __expf(2.0f * v);
    return 1.0f - __fdividef(2.0f, e + 1.0f);
}
__device__ __forceinline__ float2 ldg2(const float* p, bool v) {
    float2 r = make_float2(0.0f, 0.0f);
    if (v) r = *reinterpret_cast<const float2*>(p);
    return r;
}
__device__ __forceinline__ void mma16816(float c[4], const u32 a[4], uint2 b) {
    asm volatile(
        "mma.sync.aligned.m16n8k16.row.col.f32.bf16.bf16.f32 "
        "{%0,%1,%2,%3}, {%4,%5,%6,%7}, {%8,%9}, {%0,%1,%2,%3};"
        : "+f"(c[0]), "+f"(c[1]), "+f"(c[2]), "+f"(c[3])
        : "r"(a[0]), "r"(a[1]), "r"(a[2]), "r"(a[3]), "r"(b.x), "r"(b.y));
}

/* ====== prep: fold w0+w1, split hi/lo, emit lane-ordered B fragments ====== */
__global__ void rgcn_prep(const float* __restrict__ wz, const float* __restrict__ wr,
                          const float* __restrict__ wh, const float* __restrict__ wl) {
    int idx = blockIdx.x * blockDim.x + threadIdx.x;
    if (idx >= 38 * 32) return;
    int lane = idx & 31, fid = idx >> 5;
    int gid = lane >> 2, ctg = lane & 3;

    int kt, nt, which;
    uint2* dsth; uint2* dstl; int slot;
    if (fid < 24)      { kt = fid >> 3; nt = fid & 7;            which = 0; dsth = gBzr_h; dstl = gBzr_l; slot = fid * 32 + lane; }
    else if (fid < 36) { int f = fid - 24; kt = f >> 2; nt = f & 3; which = 1; dsth = gBh_h; dstl = gBh_l; slot = f * 32 + lane; }
    else               { kt = fid - 36; nt = 0;                  which = 2; dsth = gBl_h;  dstl = gBl_l;  slot = kt * 32 + lane; }

    int n = nt * 8 + gid;
    float v[4];
    #pragma unroll
    for (int p = 0; p < 4; p++) {
        int k = kt * 16 + ctg * 2 + (p & 1) + ((p >> 1) * 8);
        float val;
        if (which == 0) {
            if (n < 32) val = wz[k * 32 + n] + wz[1536 + k * 32 + n];
            else        val = wr[k * 32 + (n - 32)] + wr[1536 + k * 32 + (n - 32)];
        } else if (which == 1) {
            val = wh[k * 32 + n] + wh[1536 + k * 32 + n];
        } else {
            val = wl[k * 8 + n];
        }
        v[p] = val;
    }
    uint2 hi, lo;
    split2(v[0], v[1], hi.x, lo.x);
    split2(v[2], v[3], hi.y, lo.y);
    dsth[slot] = hi;
    dstl[slot] = lo;
}

/* ====== main fused kernel: zero smem, fragment-resident GRU ====== */
__global__ void __launch_bounds__(TPB) rgcn_mma_kernel(
    const float* __restrict__ x, const float* __restrict__ h,
    const float* __restrict__ bz, const float* __restrict__ br,
    const float* __restrict__ bh, const float* __restrict__ bl,
    float* __restrict__ out, float* __restrict__ hnew, int N)
{
    const int tid  = threadIdx.x;
    const int lane = tid & 31;
    const int warp = tid >> 5;
    const int gid  = lane >> 2, ctg = lane & 3;
    const int c2g  = 2 * ctg;
    const int rowBase = blockIdx.x * TILE_M + warp * 32;

    int  rw[2][2];
    bool vv[2][2];
    #pragma unroll
    for (int mt = 0; mt < 2; mt++)
        #pragma unroll
        for (int hf = 0; hf < 2; hf++) {
            rw[mt][hf] = rowBase + mt * 16 + gid + hf * 8;
            vv[mt][hf] = rw[mt][hf] < N;
        }

    /* ---- direct fragment-coordinate loads of x and h (h doubles as h_old) ---- */
    float2 xa[2][4];   /* j: 0=(r,c) 1=(r+8,c) 2=(r,c+8) 3=(r+8,c+8) */
    float2 ha[2][8];   /* q = nt*2 + rowhalf, col = nt*8 + c2g */
    #pragma unroll
    for (int mt = 0; mt < 2; mt++) {
        xa[mt][0] = ldg2(x + (size_t)rw[mt][0] * IN_DIM + c2g,     vv[mt][0]);
        xa[mt][1] = ldg2(x + (size_t)rw[mt][1] * IN_DIM + c2g,     vv[mt][1]);
        xa[mt][2] = ldg2(x + (size_t)rw[mt][0] * IN_DIM + c2g + 8, vv[mt][0]);
        xa[mt][3] = ldg2(x + (size_t)rw[mt][1] * IN_DIM + c2g + 8, vv[mt][1]);
        #pragma unroll
        for (int nt = 0; nt < 4; nt++) {
            ha[mt][nt * 2 + 0] = ldg2(h + (size_t)rw[mt][0] * HID + nt * 8 + c2g, vv[mt][0]);
            ha[mt][nt * 2 + 1] = ldg2(h + (size_t)rw[mt][1] * HID + nt * 8 + c2g, vv[mt][1]);
        }
    }

    /* ---- GEMM1: C1[128x64] = [x|h] @ B_zr ---- */
    float c1[2][8][4];
    #pragma unroll
    for (int mt = 0; mt < 2; mt++)
        #pragma unroll
        for (int nt = 0; nt < 8; nt++)
            #pragma unroll
            for (int i = 0; i < 4; i++) c1[mt][nt][i] = 0.0f;

    #pragma unroll
    for (int kt = 0; kt < 3; kt++) {
        u32 ah[2][4], al[2][4];
        #pragma unroll
        for (int mt = 0; mt < 2; mt++)
            #pragma unroll
            for (int j = 0; j < 4; j++) {
                float2 v = (kt == 0) ? xa[mt][j] : ha[mt][(kt - 1) * 4 + j];
                splitf2(v.x, v.y, ah[mt][j], al[mt][j]);
            }
        #pragma unroll
        for (int nt = 0; nt < 8; nt++) {
            uint2 Bh = __ldg(&gBzr_h[(kt * 8 + nt) * 32 + lane]);
            uint2 Bl = __ldg(&gBzr_l[(kt * 8 + nt) * 32 + lane]);
            #pragma unroll
            for (int mt = 0; mt < 2; mt++) {
                mma16816(c1[mt][nt], ah[mt], Bh);
                mma16816(c1[mt][nt], al[mt], Bh);
                mma16816(c1[mt][nt], ah[mt], Bl);
            }
        }
    }

    /* ---- epilogue 1: a2 = h * sigmoid(r); repack lane-locally into A-frags ---- */
    u32 a2h[2][8], a2l[2][8];
    #pragma unroll
    for (int nt = 0; nt < 4; nt++) {
        float2 brv = *reinterpret_cast<const float2*>(br + nt * 8 + c2g);
        #pragma unroll
        for (int mt = 0; mt < 2; mt++) {
            float r0 = sigm(c1[mt][nt + 4][0] + brv.x);
            float r1 = sigm(c1[mt][nt + 4][1] + brv.y);
            float r2 = sigm(c1[mt][nt + 4][2] + brv.x);
            float r3 = sigm(c1[mt][nt + 4][3] + brv.y);
            float a0 = ha[mt][nt * 2 + 0].x * r0;
            float a1 = ha[mt][nt * 2 + 0].y * r1;
            float a2v = ha[mt][nt * 2 + 1].x * r2;
            float a3 = ha[mt][nt * 2 + 1].y * r3;
            splitf2(a0, a1,  a2h[mt][nt * 2 + 0], a2l[mt][nt * 2 + 0]);
            splitf2(a2v, a3, a2h[mt][nt * 2 + 1], a2l[mt][nt * 2 + 1]);
        }
    }

    /* ---- GEMM2: C2[128x32] = [x | a2] @ B_h ---- */
    float cc2[2][4][4];
    #pragma unroll
    for (int mt = 0; mt < 2; mt++)
        #pragma unroll
        for (int nt = 0; nt < 4; nt++)
            #pragma unroll
            for (int i = 0; i < 4; i++) cc2[mt][nt][i] = 0.0f;

    #pragma unroll
    for (int kt = 0; kt < 3; kt++) {
        u32 ah[2][4], al[2][4];
        #pragma unroll
        for (int mt = 0; mt < 2; mt++)
            #pragma unroll
            for (int j = 0; j < 4; j++) {
                if (kt == 0) {
                    splitf2(xa[mt][j].x, xa[mt][j].y, ah[mt][j], al[mt][j]);
                } else {
                    ah[mt][j] = a2h[mt][(kt - 1) * 4 + j];
                    al[mt][j] = a2l[mt][(kt - 1) * 4 + j];
                }
            }
        #pragma unroll
        for (int nt = 0; nt < 4; nt++) {
            uint2 Bh = __ldg(&gBh_h[(kt * 4 + nt) * 32 + lane]);
            uint2 Bl = __ldg(&gBh_l[(kt * 4 + nt) * 32 + lane]);
            #pragma unroll
            for (int mt = 0; mt < 2; mt++) {
                mma16816(cc2[mt][nt], ah[mt], Bh);
                mma16816(cc2[mt][nt], al[mt], Bh);
                mma16816(cc2[mt][nt], ah[mt], Bl);
            }
        }
    }

    /* ---- epilogue 2: hn = z*h + (1-z)*tanh(c2+bh); store; repack relu(hn) ---- */
    u32 rh[2][8], rl[2][8];
    #pragma unroll
    for (int nt = 0; nt < 4; nt++) {
        float2 bzv = *reinterpret_cast<const float2*>(bz + nt * 8 + c2g);
        float2 bhv = *reinterpret_cast<const float2*>(bh + nt * 8 + c2g);
        #pragma unroll
        for (int mt = 0; mt < 2; mt++) {
            float hn[4];
            #pragma unroll
            for (int i = 0; i < 4; i++) {
                float bzi = (i & 1) ? bzv.y : bzv.x;
                float bhi = (i & 1) ? bhv.y : bhv.x;
                float hv  = (i < 2) ? ((i & 1) ? ha[mt][nt * 2 + 0].y : ha[mt][nt * 2 + 0].x)
                                    : ((i & 1) ? ha[mt][nt * 2 + 1].y : ha[mt][nt * 2 + 1].x);
                float zg = sigm(c1[mt][nt][i] + bzi);
                float ht = tanh_fast(cc2[mt][nt][i] + bhi);
                hn[i] = zg * hv + (1.0f - zg) * ht;
            }
            if (vv[mt][0])
                *reinterpret_cast<float2*>(hnew + (size_t)rw[mt][0] * HID + nt * 8 + c2g) =
                    make_float2(hn[0], hn[1]);
            if (vv[mt][1])
                *reinterpret_cast<float2*>(hnew + (size_t)rw[mt][1] * HID + nt * 8 + c2g) =
                    make_float2(hn[2], hn[3]);
            splitf2(fmaxf(hn[0], 0.0f), fmaxf(hn[1], 0.0f), rh[mt][nt * 2 + 0], rl[mt][nt * 2 + 0]);
            splitf2(fmaxf(hn[2], 0.0f), fmaxf(hn[3], 0.0f), rh[mt][nt * 2 + 1], rl[mt][nt * 2 + 1]);
        }
    }

    /* ---- GEMM3: out[128x8] = relu(hn) @ w_lin ---- */
    float co[2][4];
    #pragma unroll
    for (int mt = 0; mt < 2; mt++)
        #pragma unroll
        for (int i = 0; i < 4; i++) co[mt][i] = 0.0f;

    #pragma unroll
    for (int kt = 0; kt < 2; kt++) {
        uint2 Bh = __ldg(&gBl_h[kt * 32 + lane]);
        uint2 Bl = __ldg(&gBl_l[kt * 32 + lane]);
        #pragma unroll
        for (int mt = 0; mt < 2; mt++) {
            u32 ah[4] = { rh[mt][kt * 4 + 0], rh[mt][kt * 4 + 1],
                          rh[mt][kt * 4 + 2], rh[mt][kt * 4 + 3] };
            u32 al[4] = { rl[mt][kt * 4 + 0], rl[mt][kt * 4 + 1],
                          rl[mt][kt * 4 + 2], rl[mt][kt * 4 + 3] };
            mma16816(co[mt], ah, Bh);
            mma16816(co[mt], al, Bh);
            mma16816(co[mt], ah, Bl);
        }
    }

    float2 blv = *reinterpret_cast<const float2*>(bl + c2g);
    #pragma unroll
    for (int mt = 0; mt < 2; mt++) {
        if (vv[mt][0])
            *reinterpret_cast<float2*>(out + (size_t)rw[mt][0] * OUT_DIM + c2g) =
                make_float2(co[mt][0] + blv.x, co[mt][1] + blv.y);
        if (vv[mt][1])
            *reinterpret_cast<float2*>(out + (size_t)rw[mt][1] * OUT_DIM + c2g) =
                make_float2(co[mt][2] + blv.x, co[mt][3] + blv.y);
    }
}

extern "C" void kernel_launch(void* const* d_in, const int* in_sizes, int n_in,
                              void* d_out, int out_size) {
    const float* x  = (const float*)d_in[0];
    const float* h  = (const float*)d_in[3];
    const float* wz = (const float*)d_in[4];
    const float* bz = (const float*)d_in[5];
    const float* wr = (const float*)d_in[6];
    const float* br = (const float*)d_in[7];
    const float* wh = (const float*)d_in[8];
    const float* bh = (const float*)d_in[9];
    const float* wl = (const float*)d_in[10];
    const float* bl = (const float*)d_in[11];

    int N = in_sizes[0] / IN_DIM;
    float* out  = (float*)d_out;
    float* hnew = out + (size_t)N * OUT_DIM;

    rgcn_prep<<<5, 256>>>(wz, wr, wh, wl);

    int grid = (N + TILE_M - 1) / TILE_M;
    rgcn_mma_kernel<<<grid, TPB>>>(x, h, bz, br, bh, bl, out, hnew, N);
}

// round 5
// speedup vs baseline: 3.0587x; 1.2530x over previous
#include <cuda_runtime.h>
#include <cuda_bf16.h>
#include <cstdint>

typedef uint32_t u32;

#define IN_DIM 16
#define HID 32
#define OUT_DIM 8
#define TPB 128
#define TILE_M 64   /* 4 warps x 16 rows */

/* ------------- fragment-ordered, pre-split weight tables ------------- */
__device__ uint2 gBzr_h[768], gBzr_l[768];
__device__ uint2 gBh_h[384],  gBh_l[384];
__device__ uint2 gBl_h[64],   gBl_l[64];

/* ---------------- helpers ---------------- */
__device__ __forceinline__ u32 pkbf(float a, float b) {   /* lo=a, hi=b */
    u32 r;
    asm("cvt.rn.bf16x2.f32 %0, %1, %2;" : "=r"(r) : "f"(b), "f"(a));
    return r;
}
__device__ __forceinline__ void splitf2(float a, float b, u32 &hi, u32 &lo) {
    hi = pkbf(a, b);
    float f0 = __uint_as_float(hi << 16);
    float f1 = __uint_as_float(hi & 0xFFFF0000u);
    lo = pkbf(a - f0, b - f1);
}
__device__ __forceinline__ void split2(float a, float b, u32 &hi, u32 &lo) {
    __nv_bfloat16 ha = __float2bfloat16_rn(a), hb = __float2bfloat16_rn(b);
    __nv_bfloat16 la = __float2bfloat16_rn(a - __bfloat162float(ha));
    __nv_bfloat16 lb = __float2bfloat16_rn(b - __bfloat162float(hb));
    __nv_bfloat162 H; H.x = ha; H.y = hb;
    __nv_bfloat162 L; L.x = la; L.y = lb;
    hi = *reinterpret_cast<u32*>(&H);
    lo = *reinterpret_cast<u32*>(&L);
}
__device__ __forceinline__ float sigm(float v) {
    return __fdividef(1.0f, 1.0f + __expf(-v));
}
__device__ __forceinline__ float tanh_fast(float v) {
    float e = __expf(2.0f * v);
    return 1.0f - __fdividef(2.0f, e + 1.0f);
}
__device__ __forceinline__ float2 ldg2(const float* p, bool v) {
    float2 r = make_float2(0.0f, 0.0f);
    if (v) r = *reinterpret_cast<const float2*>(p);
    return r;
}
__device__ __forceinline__ void mma16816(float c[4], const u32 a[4], uint2 b) {
    asm volatile(
        "mma.sync.aligned.m16n8k16.row.col.f32.bf16.bf16.f32 "
        "{%0,%1,%2,%3}, {%4,%5,%6,%7}, {%8,%9}, {%0,%1,%2,%3};"
        : "+f"(c[0]), "+f"(c[1]), "+f"(c[2]), "+f"(c[3])
        : "r"(a[0]), "r"(a[1]), "r"(a[2]), "r"(a[3]), "r"(b.x), "r"(b.y));
}

/* ====== prep: fold w0+w1, split hi/lo, emit lane-ordered B fragments ====== */
__global__ void rgcn_prep(const float* __restrict__ wz, const float* __restrict__ wr,
                          const float* __restrict__ wh, const float* __restrict__ wl) {
    int idx = blockIdx.x * blockDim.x + threadIdx.x;
    if (idx >= 38 * 32) return;
    int lane = idx & 31, fid = idx >> 5;
    int gid = lane >> 2, ctg = lane & 3;

    int kt, nt, which;
    uint2* dsth; uint2* dstl; int slot;
    if (fid < 24)      { kt = fid >> 3; nt = fid & 7;            which = 0; dsth = gBzr_h; dstl = gBzr_l; slot = fid * 32 + lane; }
    else if (fid < 36) { int f = fid - 24; kt = f >> 2; nt = f & 3; which = 1; dsth = gBh_h; dstl = gBh_l; slot = f * 32 + lane; }
    else               { kt = fid - 36; nt = 0;                  which = 2; dsth = gBl_h;  dstl = gBl_l;  slot = kt * 32 + lane; }

    int n = nt * 8 + gid;
    float v[4];
    #pragma unroll
    for (int p = 0; p < 4; p++) {
        int k = kt * 16 + ctg * 2 + (p & 1) + ((p >> 1) * 8);
        float val;
        if (which == 0) {
            if (n < 32) val = wz[k * 32 + n] + wz[1536 + k * 32 + n];
            else        val = wr[k * 32 + (n - 32)] + wr[1536 + k * 32 + (n - 32)];
        } else if (which == 1) {
            val = wh[k * 32 + n] + wh[1536 + k * 32 + n];
        } else {
            val = wl[k * 8 + n];
        }
        v[p] = val;
    }
    uint2 hi, lo;
    split2(v[0], v[1], hi.x, lo.x);
    split2(v[2], v[3], hi.y, lo.y);
    dsth[slot] = hi;
    dstl[slot] = lo;
}

/* ====== main fused kernel: zero smem, fragment-resident GRU, 1 m-tile/warp == */
__global__ void __launch_bounds__(TPB, 4) rgcn_mma_kernel(
    const float* __restrict__ x, const float* __restrict__ h,
    const float* __restrict__ bz, const float* __restrict__ br,
    const float* __restrict__ bh, const float* __restrict__ bl,
    float* __restrict__ out, float* __restrict__ hnew, int N)
{
    const int tid  = threadIdx.x;
    const int lane = tid & 31;
    const int warp = tid >> 5;
    const int gid  = lane >> 2, ctg = lane & 3;
    const int c2g  = 2 * ctg;
    const int rowBase = blockIdx.x * TILE_M + warp * 16;

    const int  r0 = rowBase + gid;
    const int  r1 = r0 + 8;
    const bool v0 = r0 < N;
    const bool v1 = r1 < N;

    /* ---- direct fragment-coordinate loads of x and h (h doubles as h_old) ---- */
    float2 xa[4];   /* j: 0=(r0,c) 1=(r1,c) 2=(r0,c+8) 3=(r1,c+8) */
    float2 ha[8];   /* q = nt*2 + rowhalf, col = nt*8 + c2g */
    xa[0] = ldg2(x + (size_t)r0 * IN_DIM + c2g,     v0);
    xa[1] = ldg2(x + (size_t)r1 * IN_DIM + c2g,     v1);
    xa[2] = ldg2(x + (size_t)r0 * IN_DIM + c2g + 8, v0);
    xa[3] = ldg2(x + (size_t)r1 * IN_DIM + c2g + 8, v1);
    #pragma unroll
    for (int nt = 0; nt < 4; nt++) {
        ha[nt * 2 + 0] = ldg2(h + (size_t)r0 * HID + nt * 8 + c2g, v0);
        ha[nt * 2 + 1] = ldg2(h + (size_t)r1 * HID + nt * 8 + c2g, v1);
    }

    /* x fragments split once, reused by GEMM1 and GEMM2 */
    u32 xh[4], xl[4];
    #pragma unroll
    for (int j = 0; j < 4; j++) splitf2(xa[j].x, xa[j].y, xh[j], xl[j]);

    /* ---- GEMM1: C1[16x64] = [x|h] @ B_zr ---- */
    float c1[8][4];
    #pragma unroll
    for (int nt = 0; nt < 8; nt++)
        #pragma unroll
        for (int i = 0; i < 4; i++) c1[nt][i] = 0.0f;

    #pragma unroll
    for (int kt = 0; kt < 3; kt++) {
        u32 ah[4], al[4];
        #pragma unroll
        for (int j = 0; j < 4; j++) {
            if (kt == 0) { ah[j] = xh[j]; al[j] = xl[j]; }
            else splitf2(ha[(kt - 1) * 4 + j].x, ha[(kt - 1) * 4 + j].y, ah[j], al[j]);
        }
        #pragma unroll
        for (int nt = 0; nt < 8; nt++) {
            uint2 Bh = __ldg(&gBzr_h[(kt * 8 + nt) * 32 + lane]);
            uint2 Bl = __ldg(&gBzr_l[(kt * 8 + nt) * 32 + lane]);
            mma16816(c1[nt], ah, Bh);
            mma16816(c1[nt], al, Bh);
            mma16816(c1[nt], ah, Bl);
        }
    }

    /* ---- epilogue 1: a2 = h * sigmoid(r); repack lane-locally into A-frags ---- */
    u32 a2h[8], a2l[8];
    #pragma unroll
    for (int nt = 0; nt < 4; nt++) {
        float2 brv = *reinterpret_cast<const float2*>(br + nt * 8 + c2g);
        float rr0 = sigm(c1[nt + 4][0] + brv.x);
        float rr1 = sigm(c1[nt + 4][1] + brv.y);
        float rr2 = sigm(c1[nt + 4][2] + brv.x);
        float rr3 = sigm(c1[nt + 4][3] + brv.y);
        float a0 = ha[nt * 2 + 0].x * rr0;
        float a1 = ha[nt * 2 + 0].y * rr1;
        float a2v = ha[nt * 2 + 1].x * rr2;
        float a3 = ha[nt * 2 + 1].y * rr3;
        splitf2(a0, a1,  a2h[nt * 2 + 0], a2l[nt * 2 + 0]);
        splitf2(a2v, a3, a2h[nt * 2 + 1], a2l[nt * 2 + 1]);
    }

    /* ---- GEMM2: C2[16x32] = [x | a2] @ B_h ---- */
    float cc2[4][4];
    #pragma unroll
    for (int nt = 0; nt < 4; nt++)
        #pragma unroll
        for (int i = 0; i < 4; i++) cc2[nt][i] = 0.0f;

    #pragma unroll
    for (int kt = 0; kt < 3; kt++) {
        u32 ah[4], al[4];
        #pragma unroll
        for (int j = 0; j < 4; j++) {
            if (kt == 0) { ah[j] = xh[j]; al[j] = xl[j]; }
            else         { ah[j] = a2h[(kt - 1) * 4 + j]; al[j] = a2l[(kt - 1) * 4 + j]; }
        }
        #pragma unroll
        for (int nt = 0; nt < 4; nt++) {
            uint2 Bh = __ldg(&gBh_h[(kt * 4 + nt) * 32 + lane]);
            uint2 Bl = __ldg(&gBh_l[(kt * 4 + nt) * 32 + lane]);
            mma16816(cc2[nt], ah, Bh);
            mma16816(cc2[nt], al, Bh);
            mma16816(cc2[nt], ah, Bl);
        }
    }

    /* ---- epilogue 2: hn = z*h + (1-z)*tanh(c2+bh); store; repack relu(hn) ---- */
    u32 rh[8], rl[8];
    #pragma unroll
    for (int nt = 0; nt < 4; nt++) {
        float2 bzv = *reinterpret_cast<const float2*>(bz + nt * 8 + c2g);
        float2 bhv = *reinterpret_cast<const float2*>(bh + nt * 8 + c2g);
        float hn[4];
        #pragma unroll
        for (int i = 0; i < 4; i++) {
            float bzi = (i & 1) ? bzv.y : bzv.x;
            float bhi = (i & 1) ? bhv.y : bhv.x;
            float hv  = (i < 2) ? ((i & 1) ? ha[nt * 2 + 0].y : ha[nt * 2 + 0].x)
                                : ((i & 1) ? ha[nt * 2 + 1].y : ha[nt * 2 + 1].x);
            float zg = sigm(c1[nt][i] + bzi);
            float ht = tanh_fast(cc2[nt][i] + bhi);
            hn[i] = zg * hv + (1.0f - zg) * ht;
        }
        if (v0)
            *reinterpret_cast<float2*>(hnew + (size_t)r0 * HID + nt * 8 + c2g) =
                make_float2(hn[0], hn[1]);
        if (v1)
            *reinterpret_cast<float2*>(hnew + (size_t)r1 * HID + nt * 8 + c2g) =
                make_float2(hn[2], hn[3]);
        splitf2(fmaxf(hn[0], 0.0f), fmaxf(hn[1], 0.0f), rh[nt * 2 + 0], rl[nt * 2 + 0]);
        splitf2(fmaxf(hn[2], 0.0f), fmaxf(hn[3], 0.0f), rh[nt * 2 + 1], rl[nt * 2 + 1]);
    }

    /* ---- GEMM3: out[16x8] = relu(hn) @ w_lin ---- */
    float co[4] = {0.0f, 0.0f, 0.0f, 0.0f};
    #pragma unroll
    for (int kt = 0; kt < 2; kt++) {
        uint2 Bh = __ldg(&gBl_h[kt * 32 + lane]);
        uint2 Bl = __ldg(&gBl_l[kt * 32 + lane]);
        u32 ah[4] = { rh[kt * 4 + 0], rh[kt * 4 + 1], rh[kt * 4 + 2], rh[kt * 4 + 3] };
        u32 al[4] = { rl[kt * 4 + 0], rl[kt * 4 + 1], rl[kt * 4 + 2], rl[kt * 4 + 3] };
        mma16816(co, ah, Bh);
        mma16816(co, al, Bh);
        mma16816(co, ah, Bl);
    }

    float2 blv = *reinterpret_cast<const float2*>(bl + c2g);
    if (v0)
        *reinterpret_cast<float2*>(out + (size_t)r0 * OUT_DIM + c2g) =
            make_float2(co[0] + blv.x, co[1] + blv.y);
    if (v1)
        *reinterpret_cast<float2*>(out + (size_t)r1 * OUT_DIM + c2g) =
            make_float2(co[2] + blv.x, co[3] + blv.y);
}

extern "C" void kernel_launch(void* const* d_in, const int* in_sizes, int n_in,
                              void* d_out, int out_size) {
    const float* x  = (const float*)d_in[0];
    const float* h  = (const float*)d_in[3];
    const float* wz = (const float*)d_in[4];
    const float* bz = (const float*)d_in[5];
    const float* wr = (const float*)d_in[6];
    const float* br = (const float*)d_in[7];
    const float* wh = (const float*)d_in[8];
    const float* bh = (const float*)d_in[9];
    const float* wl = (const float*)d_in[10];
    const float* bl = (const float*)d_in[11];

    int N = in_sizes[0] / IN_DIM;
    float* out  = (float*)d_out;
    float* hnew = out + (size_t)N * OUT_DIM;

    rgcn_prep<<<5, 256>>>(wz, wr, wh, wl);

    int grid = (N + TILE_M - 1) / TILE_M;
    rgcn_mma_kernel<<<grid, TPB>>>(x, h, bz, br, bh, bl, out, hnew, N);
}

// round 6
// speedup vs baseline: 3.3328x; 1.0896x over previous
#include <cuda_runtime.h>
#include <cuda_bf16.h>
#include <cstdint>

typedef uint32_t u32;

#define IN_DIM 16
#define HID 32
#define OUT_DIM 8
#define TPB 128
#define TILE_M 64   /* 4 warps x 16 rows */

/* ---- fragment-ordered weight tables: uint4 = {Bh.x, Bh.y, Bl.x, Bl.y} ---- */
__device__ uint4 gBzr[768];   /* 24 frags x 32 lanes */
__device__ uint4 gBh[384];    /* 12 frags x 32 lanes */
__device__ uint4 gBl[64];     /*  2 frags x 32 lanes */

/* ---------------- helpers ---------------- */
__device__ __forceinline__ u32 pkbf(float a, float b) {   /* lo=a, hi=b */
    u32 r;
    asm("cvt.rn.bf16x2.f32 %0, %1, %2;" : "=r"(r) : "f"(b), "f"(a));
    return r;
}
__device__ __forceinline__ void splitf2(float a, float b, u32 &hi, u32 &lo) {
    hi = pkbf(a, b);
    float f0 = __uint_as_float(hi << 16);
    float f1 = __uint_as_float(hi & 0xFFFF0000u);
    lo = pkbf(a - f0, b - f1);
}
__device__ __forceinline__ void split2(float a, float b, u32 &hi, u32 &lo) {
    __nv_bfloat16 ha = __float2bfloat16_rn(a), hb = __float2bfloat16_rn(b);
    __nv_bfloat16 la = __float2bfloat16_rn(a - __bfloat162float(ha));
    __nv_bfloat16 lb = __float2bfloat16_rn(b - __bfloat162float(hb));
    __nv_bfloat162 H; H.x = ha; H.y = hb;
    __nv_bfloat162 L; L.x = la; L.y = lb;
    hi = *reinterpret_cast<u32*>(&H);
    lo = *reinterpret_cast<u32*>(&L);
}
__device__ __forceinline__ float tanh_hw(float x) {
    float y;
    asm("tanh.approx.f32 %0, %1;" : "=f"(y) : "f"(x));
    return y;
}
__device__ __forceinline__ float sigm(float v) {
    return fmaf(tanh_hw(0.5f * v), 0.5f, 0.5f);
}
__device__ __forceinline__ float2 ldg2(const float* p, bool v) {
    float2 r = make_float2(0.0f, 0.0f);
    if (v) r = *reinterpret_cast<const float2*>(p);
    return r;
}
__device__ __forceinline__ void mma16816(float c[4], const u32 a[4], u32 b0, u32 b1) {
    asm volatile(
        "mma.sync.aligned.m16n8k16.row.col.f32.bf16.bf16.f32 "
        "{%0,%1,%2,%3}, {%4,%5,%6,%7}, {%8,%9}, {%0,%1,%2,%3};"
        : "+f"(c[0]), "+f"(c[1]), "+f"(c[2]), "+f"(c[3])
        : "r"(a[0]), "r"(a[1]), "r"(a[2]), "r"(a[3]), "r"(b0), "r"(b1));
}
/* 3-product split MMA with interleaved B: AhBh + AlBh + AhBl */
__device__ __forceinline__ void mma3(float c[4], const u32 ah[4], const u32 al[4], uint4 B) {
    mma16816(c, ah, B.x, B.y);
    mma16816(c, al, B.x, B.y);
    mma16816(c, ah, B.z, B.w);
}

/* ====== prep: fold w0+w1, split hi/lo, emit lane-ordered B fragments ====== */
__global__ void rgcn_prep(const float* __restrict__ wz, const float* __restrict__ wr,
                          const float* __restrict__ wh, const float* __restrict__ wl) {
    int idx = blockIdx.x * blockDim.x + threadIdx.x;
    if (idx >= 38 * 32) return;
    int lane = idx & 31, fid = idx >> 5;
    int gid = lane >> 2, ctg = lane & 3;

    int kt, nt, which;
    uint4* dst; int slot;
    if (fid < 24)      { kt = fid >> 3; nt = fid & 7;            which = 0; dst = gBzr; slot = fid * 32 + lane; }
    else if (fid < 36) { int f = fid - 24; kt = f >> 2; nt = f & 3; which = 1; dst = gBh; slot = f * 32 + lane; }
    else               { kt = fid - 36; nt = 0;                  which = 2; dst = gBl;  slot = kt * 32 + lane; }

    int n = nt * 8 + gid;
    float v[4];
    #pragma unroll
    for (int p = 0; p < 4; p++) {
        int k = kt * 16 + ctg * 2 + (p & 1) + ((p >> 1) * 8);
        float val;
        if (which == 0) {
            if (n < 32) val = wz[k * 32 + n] + wz[1536 + k * 32 + n];
            else        val = wr[k * 32 + (n - 32)] + wr[1536 + k * 32 + (n - 32)];
        } else if (which == 1) {
            val = wh[k * 32 + n] + wh[1536 + k * 32 + n];
        } else {
            val = wl[k * 8 + n];
        }
        v[p] = val;
    }
    uint4 o;
    split2(v[0], v[1], o.x, o.z);
    split2(v[2], v[3], o.y, o.w);
    dst[slot] = o;
}

/* ====== main fused kernel: zero smem, fragment-resident GRU, 1 m-tile/warp == */
__global__ void __launch_bounds__(TPB, 4) rgcn_mma_kernel(
    const float* __restrict__ x, const float* __restrict__ h,
    const float* __restrict__ bz, const float* __restrict__ br,
    const float* __restrict__ bh, const float* __restrict__ bl,
    float* __restrict__ out, float* __restrict__ hnew, int N)
{
    const int tid  = threadIdx.x;
    const int lane = tid & 31;
    const int warp = tid >> 5;
    const int gid  = lane >> 2, ctg = lane & 3;
    const int c2g  = 2 * ctg;
    const int rowBase = blockIdx.x * TILE_M + warp * 16;

    const int  r0 = rowBase + gid;
    const int  r1 = r0 + 8;
    const bool v0 = r0 < N;
    const bool v1 = r1 < N;

    /* ---- direct fragment-coordinate loads of x and h (h doubles as h_old) ---- */
    float2 xa[4];   /* j: 0=(r0,c) 1=(r1,c) 2=(r0,c+8) 3=(r1,c+8) */
    float2 ha[8];   /* q = nt*2 + rowhalf, col = nt*8 + c2g */
    xa[0] = ldg2(x + (size_t)r0 * IN_DIM + c2g,     v0);
    xa[1] = ldg2(x + (size_t)r1 * IN_DIM + c2g,     v1);
    xa[2] = ldg2(x + (size_t)r0 * IN_DIM + c2g + 8, v0);
    xa[3] = ldg2(x + (size_t)r1 * IN_DIM + c2g + 8, v1);
    #pragma unroll
    for (int nt = 0; nt < 4; nt++) {
        ha[nt * 2 + 0] = ldg2(h + (size_t)r0 * HID + nt * 8 + c2g, v0);
        ha[nt * 2 + 1] = ldg2(h + (size_t)r1 * HID + nt * 8 + c2g, v1);
    }

    /* x fragments split once, reused by GEMM1 and GEMM2 */
    u32 xh[4], xl[4];
    #pragma unroll
    for (int j = 0; j < 4; j++) splitf2(xa[j].x, xa[j].y, xh[j], xl[j]);

    /* ---- GEMM1: C1[16x64] = [x|h] @ B_zr ---- */
    float c1[8][4];
    #pragma unroll
    for (int nt = 0; nt < 8; nt++)
        #pragma unroll
        for (int i = 0; i < 4; i++) c1[nt][i] = 0.0f;

    #pragma unroll
    for (int kt = 0; kt < 3; kt++) {
        u32 ah[4], al[4];
        #pragma unroll
        for (int j = 0; j < 4; j++) {
            if (kt == 0) { ah[j] = xh[j]; al[j] = xl[j]; }
            else splitf2(ha[(kt - 1) * 4 + j].x, ha[(kt - 1) * 4 + j].y, ah[j], al[j]);
        }
        #pragma unroll
        for (int nt = 0; nt < 8; nt++) {
            uint4 B = __ldg(&gBzr[(kt * 8 + nt) * 32 + lane]);
            mma3(c1[nt], ah, al, B);
        }
    }

    /* ---- epilogue 1: a2 = h * sigmoid(r); repack lane-locally into A-frags ---- */
    u32 a2h[8], a2l[8];
    #pragma unroll
    for (int nt = 0; nt < 4; nt++) {
        float2 brv = *reinterpret_cast<const float2*>(br + nt * 8 + c2g);
        float rr0 = sigm(c1[nt + 4][0] + brv.x);
        float rr1 = sigm(c1[nt + 4][1] + brv.y);
        float rr2 = sigm(c1[nt + 4][2] + brv.x);
        float rr3 = sigm(c1[nt + 4][3] + brv.y);
        float a0 = ha[nt * 2 + 0].x * rr0;
        float a1 = ha[nt * 2 + 0].y * rr1;
        float a2v = ha[nt * 2 + 1].x * rr2;
        float a3 = ha[nt * 2 + 1].y * rr3;
        splitf2(a0, a1,  a2h[nt * 2 + 0], a2l[nt * 2 + 0]);
        splitf2(a2v, a3, a2h[nt * 2 + 1], a2l[nt * 2 + 1]);
    }

    /* ---- GEMM2: C2[16x32] = [x | a2] @ B_h ---- */
    float cc2[4][4];
    #pragma unroll
    for (int nt = 0; nt < 4; nt++)
        #pragma unroll
        for (int i = 0; i < 4; i++) cc2[nt][i] = 0.0f;

    #pragma unroll
    for (int kt = 0; kt < 3; kt++) {
        u32 ah[4], al[4];
        #pragma unroll
        for (int j = 0; j < 4; j++) {
            if (kt == 0) { ah[j] = xh[j]; al[j] = xl[j]; }
            else         { ah[j] = a2h[(kt - 1) * 4 + j]; al[j] = a2l[(kt - 1) * 4 + j]; }
        }
        #pragma unroll
        for (int nt = 0; nt < 4; nt++) {
            uint4 B = __ldg(&gBh[(kt * 4 + nt) * 32 + lane]);
            mma3(cc2[nt], ah, al, B);
        }
    }

    /* ---- epilogue 2: hn = h̃ + z*(h - h̃); store; repack relu(hn) ---- */
    u32 rh[8], rl[8];
    #pragma unroll
    for (int nt = 0; nt < 4; nt++) {
        float2 bzv = *reinterpret_cast<const float2*>(bz + nt * 8 + c2g);
        float2 bhv = *reinterpret_cast<const float2*>(bh + nt * 8 + c2g);
        float hn[4];
        #pragma unroll
        for (int i = 0; i < 4; i++) {
            float bzi = (i & 1) ? bzv.y : bzv.x;
            float bhi = (i & 1) ? bhv.y : bhv.x;
            float hv  = (i < 2) ? ((i & 1) ? ha[nt * 2 + 0].y : ha[nt * 2 + 0].x)
                                : ((i & 1) ? ha[nt * 2 + 1].y : ha[nt * 2 + 1].x);
            float zg = sigm(c1[nt][i] + bzi);
            float ht = tanh_hw(cc2[nt][i] + bhi);
            hn[i] = fmaf(zg, hv - ht, ht);
        }
        if (v0)
            *reinterpret_cast<float2*>(hnew + (size_t)r0 * HID + nt * 8 + c2g) =
                make_float2(hn[0], hn[1]);
        if (v1)
            *reinterpret_cast<float2*>(hnew + (size_t)r1 * HID + nt * 8 + c2g) =
                make_float2(hn[2], hn[3]);
        splitf2(fmaxf(hn[0], 0.0f), fmaxf(hn[1], 0.0f), rh[nt * 2 + 0], rl[nt * 2 + 0]);
        splitf2(fmaxf(hn[2], 0.0f), fmaxf(hn[3], 0.0f), rh[nt * 2 + 1], rl[nt * 2 + 1]);
    }

    /* ---- GEMM3: out[16x8] = relu(hn) @ w_lin ---- */
    float co[4] = {0.0f, 0.0f, 0.0f, 0.0f};
    #pragma unroll
    for (int kt = 0; kt < 2; kt++) {
        uint4 B = __ldg(&gBl[kt * 32 + lane]);
        u32 ah[4] = { rh[kt * 4 + 0], rh[kt * 4 + 1], rh[kt * 4 + 2], rh[kt * 4 + 3] };
        u32 al[4] = { rl[kt * 4 + 0], rl[kt * 4 + 1], rl[kt * 4 + 2], rl[kt * 4 + 3] };
        mma3(co, ah, al, B);
    }

    float2 blv = *reinterpret_cast<const float2*>(bl + c2g);
    if (v0)
        *reinterpret_cast<float2*>(out + (size_t)r0 * OUT_DIM + c2g) =
            make_float2(co[0] + blv.x, co[1] + blv.y);
    if (v1)
        *reinterpret_cast<float2*>(out + (size_t)r1 * OUT_DIM + c2g) =
            make_float2(co[2] + blv.x, co[3] + blv.y);
}

extern "C" void kernel_launch(void* const* d_in, const int* in_sizes, int n_in,
                              void* d_out, int out_size) {
    const float* x  = (const float*)d_in[0];
    const float* h  = (const float*)d_in[3];
    const float* wz = (const float*)d_in[4];
    const float* bz = (const float*)d_in[5];
    const float* wr = (const float*)d_in[6];
    const float* br = (const float*)d_in[7];
    const float* wh = (const float*)d_in[8];
    const float* bh = (const float*)d_in[9];
    const float* wl = (const float*)d_in[10];
    const float* bl = (const float*)d_in[11];

    int N = in_sizes[0] / IN_DIM;
    float* out  = (float*)d_out;
    float* hnew = out + (size_t)N * OUT_DIM;

    rgcn_prep<<<5, 256>>>(wz, wr, wh, wl);

    int grid = (N + TILE_M - 1) / TILE_M;
    rgcn_mma_kernel<<<grid, TPB>>>(x, h, bz, br, bh, bl, out, hnew, N);
}

// round 7
// speedup vs baseline: 3.7215x; 1.1166x over previous
#include <cuda_runtime.h>
#include <cuda_bf16.h>
#include <cstdint>

typedef uint32_t u32;

#define IN_DIM 16
#define HID 32
#define OUT_DIM 8
#define TPB 128
#define TILE_M 128   /* 4 warps x 32 rows (mt=2) */

/* ---- fragment-ordered weight tables: uint4 = {Bh.x, Bh.y, Bl.x, Bl.y} ---- */
__device__ uint4 gB1[768];   /* z|r: 24 frags x 32 lanes */
__device__ uint4 gBh[384];   /* h̃ : 12 frags x 32 lanes */
__device__ uint4 gBl[64];    /* lin:  2 frags x 32 lanes */

/* ---------------- helpers ---------------- */
__device__ __forceinline__ u32 pkbf(float a, float b) {   /* lo=a, hi=b */
    u32 r;
    asm("cvt.rn.bf16x2.f32 %0, %1, %2;" : "=r"(r) : "f"(b), "f"(a));
    return r;
}
__device__ __forceinline__ void splitf2(float a, float b, u32 &hi, u32 &lo) {
    hi = pkbf(a, b);
    float f0 = __uint_as_float(hi << 16);
    float f1 = __uint_as_float(hi & 0xFFFF0000u);
    lo = pkbf(a - f0, b - f1);
}
__device__ __forceinline__ void split2(float a, float b, u32 &hi, u32 &lo) {
    __nv_bfloat16 ha = __float2bfloat16_rn(a), hb = __float2bfloat16_rn(b);
    __nv_bfloat16 la = __float2bfloat16_rn(a - __bfloat162float(ha));
    __nv_bfloat16 lb = __float2bfloat16_rn(b - __bfloat162float(hb));
    __nv_bfloat162 H; H.x = ha; H.y = hb;
    __nv_bfloat162 L; L.x = la; L.y = lb;
    hi = *reinterpret_cast<u32*>(&H);
    lo = *reinterpret_cast<u32*>(&L);
}
__device__ __forceinline__ float tanh_hw(float x) {
    float y;
    asm("tanh.approx.f32 %0, %1;" : "=f"(y) : "f"(x));
    return y;
}
__device__ __forceinline__ float sigm(float v) {
    return fmaf(tanh_hw(0.5f * v), 0.5f, 0.5f);
}
__device__ __forceinline__ void ldg4f(float* d, const float* p, bool v) {
    float4 t = make_float4(0.0f, 0.0f, 0.0f, 0.0f);
    if (v) t = *reinterpret_cast<const float4*>(p);
    d[0] = t.x; d[1] = t.y; d[2] = t.z; d[3] = t.w;
}
__device__ __forceinline__ void mma16816(float c[4], const u32 a[4], u32 b0, u32 b1) {
    asm volatile(
        "mma.sync.aligned.m16n8k16.row.col.f32.bf16.bf16.f32 "
        "{%0,%1,%2,%3}, {%4,%5,%6,%7}, {%8,%9}, {%0,%1,%2,%3};"
        : "+f"(c[0]), "+f"(c[1]), "+f"(c[2]), "+f"(c[3])
        : "r"(a[0]), "r"(a[1]), "r"(a[2]), "r"(a[3]), "r"(b0), "r"(b1));
}
__device__ __forceinline__ void mma3(float c[4], const u32 ah[4], const u32 al[4], uint4 B) {
    mma16816(c, ah, B.x, B.y);
    mma16816(c, al, B.x, B.y);
    mma16816(c, ah, B.z, B.w);
}

/* ====== prep: fold w0+w1, apply k/n permutations, split, emit fragments ====== */
/* k-permutation: MMA k-slot (ctg, p) <-> logical k = kt*16 + 4*ctg + p          */
/* n-permutation (32-col groups): slot (nt, j) <-> logical                        */
/*   n = (nt>>1)*16 + (nt&1)*2 + 4*(j>>1) + (j&1)                                 */
__global__ void rgcn_prep(const float* __restrict__ wz, const float* __restrict__ wr,
                          const float* __restrict__ wh, const float* __restrict__ wl) {
    int idx = blockIdx.x * blockDim.x + threadIdx.x;
    if (idx >= 38 * 32) return;
    int lane = idx & 31, fid = idx >> 5;
    int gid = lane >> 2, ctg = lane & 3;

    float v[4];
    if (fid < 24) {                 /* B1: z (nt 0..3) | r (nt 4..7) */
        int kt = fid >> 3, nt = fid & 7;
        int nt4 = nt & 3;
        int L = ((nt4 >> 1) << 4) + ((nt4 & 1) << 1) + ((gid >> 1) << 2) + (gid & 1);
        #pragma unroll
        for (int p = 0; p < 4; p++) {
            int k = kt * 16 + ctg * 4 + p;
            v[p] = (nt < 4) ? wz[k * 32 + L] + wz[1536 + k * 32 + L]
                            : wr[k * 32 + L] + wr[1536 + k * 32 + L];
        }
        uint4 o;
        split2(v[0], v[1], o.x, o.z);
        split2(v[2], v[3], o.y, o.w);
        gB1[fid * 32 + lane] = o;
    } else if (fid < 36) {          /* B_h */
        int f = fid - 24;
        int kt = f >> 2, nt = f & 3;
        int L = ((nt >> 1) << 4) + ((nt & 1) << 1) + ((gid >> 1) << 2) + (gid & 1);
        #pragma unroll
        for (int p = 0; p < 4; p++) {
            int k = kt * 16 + ctg * 4 + p;
            v[p] = wh[k * 32 + L] + wh[1536 + k * 32 + L];
        }
        uint4 o;
        split2(v[0], v[1], o.x, o.z);
        split2(v[2], v[3], o.y, o.w);
        gBh[f * 32 + lane] = o;
    } else {                        /* B_lin (identity n) */
        int kt = fid - 36;
        #pragma unroll
        for (int p = 0; p < 4; p++) {
            int k = kt * 16 + ctg * 4 + p;
            v[p] = wl[k * 8 + gid];
        }
        uint4 o;
        split2(v[0], v[1], o.x, o.z);
        split2(v[2], v[3], o.y, o.w);
        gBl[kt * 32 + lane] = o;
    }
}

/* ====== main fused kernel: mt=2, zero smem, fully vectorized I/O ====== */
__global__ void __launch_bounds__(TPB, 3) rgcn_mma_kernel(
    const float* __restrict__ x, const float* __restrict__ h,
    const float* __restrict__ bz, const float* __restrict__ br,
    const float* __restrict__ bh, const float* __restrict__ bl,
    float* __restrict__ out, float* __restrict__ hnew, int N)
{
    const int tid  = threadIdx.x;
    const int lane = tid & 31;
    const int warp = tid >> 5;
    const int gid  = lane >> 2, ctg = lane & 3;
    const int c4   = 4 * ctg, c2 = 2 * ctg;
    const int rowBase = blockIdx.x * TILE_M + warp * 32;

    int  rr[2][2];
    bool vv[2][2];
    #pragma unroll
    for (int mt = 0; mt < 2; mt++)
        #pragma unroll
        for (int rh = 0; rh < 2; rh++) {
            rr[mt][rh] = rowBase + mt * 16 + gid + rh * 8;
            vv[mt][rh] = rr[mt][rh] < N;
        }

    /* ---- vectorized loads at permuted fragment coordinates ---- */
    float xv[2][2][4], hA[2][2][4], hB[2][2][4];
    #pragma unroll
    for (int mt = 0; mt < 2; mt++)
        #pragma unroll
        for (int rh = 0; rh < 2; rh++) {
            ldg4f(xv[mt][rh], x + (size_t)rr[mt][rh] * IN_DIM + c4,      vv[mt][rh]);
            ldg4f(hA[mt][rh], h + (size_t)rr[mt][rh] * HID + c4,        vv[mt][rh]);
            ldg4f(hB[mt][rh], h + (size_t)rr[mt][rh] * HID + 16 + c4,   vv[mt][rh]);
        }

    /* x fragments split once */
    u32 xah[2][4], xal[2][4];
    #pragma unroll
    for (int mt = 0; mt < 2; mt++) {
        splitf2(xv[mt][0][0], xv[mt][0][1], xah[mt][0], xal[mt][0]);
        splitf2(xv[mt][1][0], xv[mt][1][1], xah[mt][1], xal[mt][1]);
        splitf2(xv[mt][0][2], xv[mt][0][3], xah[mt][2], xal[mt][2]);
        splitf2(xv[mt][1][2], xv[mt][1][3], xah[mt][3], xal[mt][3]);
    }

    /* ---- GEMM1: C1[32x64] = [x|h] @ B_zr (fused z|r) ---- */
    float c1[2][8][4];
    #pragma unroll
    for (int mt = 0; mt < 2; mt++)
        #pragma unroll
        for (int nt = 0; nt < 8; nt++)
            #pragma unroll
            for (int i = 0; i < 4; i++) c1[mt][nt][i] = 0.0f;

    #pragma unroll
    for (int kt = 0; kt < 3; kt++) {
        u32 ah[2][4], al[2][4];
        #pragma unroll
        for (int mt = 0; mt < 2; mt++) {
            if (kt == 0) {
                #pragma unroll
                for (int j = 0; j < 4; j++) { ah[mt][j] = xah[mt][j]; al[mt][j] = xal[mt][j]; }
            } else {
                const float (*hh)[4] = (kt == 1) ? hA[mt] : hB[mt];
                splitf2(hh[0][0], hh[0][1], ah[mt][0], al[mt][0]);
                splitf2(hh[1][0], hh[1][1], ah[mt][1], al[mt][1]);
                splitf2(hh[0][2], hh[0][3], ah[mt][2], al[mt][2]);
                splitf2(hh[1][2], hh[1][3], ah[mt][3], al[mt][3]);
            }
        }
        #pragma unroll
        for (int nt = 0; nt < 8; nt++) {
            uint4 B = __ldg(&gB1[(kt * 8 + nt) * 32 + lane]);
            mma3(c1[0][nt], ah[0], al[0], B);
            mma3(c1[1][nt], ah[1], al[1], B);
        }
    }

    /* ---- epilogue 1: a2 = h * sigmoid(r+br); pack straight into A-frags ---- */
    float brA[4], brB[4];
    ldg4f(brA, br + c4, true);
    ldg4f(brB, br + 16 + c4, true);

    u32 a2h[2][8], a2l[2][8];
    #pragma unroll
    for (int mt = 0; mt < 2; mt++) {
        splitf2(hA[mt][0][0] * sigm(c1[mt][4][0] + brA[0]),
                hA[mt][0][1] * sigm(c1[mt][4][1] + brA[1]), a2h[mt][0], a2l[mt][0]);
        splitf2(hA[mt][1][0] * sigm(c1[mt][4][2] + brA[0]),
                hA[mt][1][1] * sigm(c1[mt][4][3] + brA[1]), a2h[mt][1], a2l[mt][1]);
        splitf2(hA[mt][0][2] * sigm(c1[mt][5][0] + brA[2]),
                hA[mt][0][3] * sigm(c1[mt][5][1] + brA[3]), a2h[mt][2], a2l[mt][2]);
        splitf2(hA[mt][1][2] * sigm(c1[mt][5][2] + brA[2]),
                hA[mt][1][3] * sigm(c1[mt][5][3] + brA[3]), a2h[mt][3], a2l[mt][3]);
        splitf2(hB[mt][0][0] * sigm(c1[mt][6][0] + brB[0]),
                hB[mt][0][1] * sigm(c1[mt][6][1] + brB[1]), a2h[mt][4], a2l[mt][4]);
        splitf2(hB[mt][1][0] * sigm(c1[mt][6][2] + brB[0]),
                hB[mt][1][1] * sigm(c1[mt][6][3] + brB[1]), a2h[mt][5], a2l[mt][5]);
        splitf2(hB[mt][0][2] * sigm(c1[mt][7][0] + brB[2]),
                hB[mt][0][3] * sigm(c1[mt][7][1] + brB[3]), a2h[mt][6], a2l[mt][6]);
        splitf2(hB[mt][1][2] * sigm(c1[mt][7][2] + brB[2]),
                hB[mt][1][3] * sigm(c1[mt][7][3] + brB[3]), a2h[mt][7], a2l[mt][7]);
    }

    /* ---- GEMM2: CC[32x32] = [x | a2] @ B_h ---- */
    float cc[2][4][4];
    #pragma unroll
    for (int mt = 0; mt < 2; mt++)
        #pragma unroll
        for (int nt = 0; nt < 4; nt++)
            #pragma unroll
            for (int i = 0; i < 4; i++) cc[mt][nt][i] = 0.0f;

    #pragma unroll
    for (int kt = 0; kt < 3; kt++) {
        #pragma unroll
        for (int nt = 0; nt < 4; nt++) {
            uint4 B = __ldg(&gBh[(kt * 4 + nt) * 32 + lane]);
            #pragma unroll
            for (int mt = 0; mt < 2; mt++) {
                const u32* ph = (kt == 0) ? xah[mt] : &a2h[mt][(kt - 1) * 4];
                const u32* pl = (kt == 0) ? xal[mt] : &a2l[mt][(kt - 1) * 4];
                mma3(cc[mt][nt], ph, pl, B);
            }
        }
    }

    /* ---- epilogue 2: hn = h̃ + z*(h - h̃); float4 stores; repack relu(hn) ---- */
    float bzA[4], bzB[4], bhA[4], bhB[4];
    ldg4f(bzA, bz + c4, true);
    ldg4f(bzB, bz + 16 + c4, true);
    ldg4f(bhA, bh + c4, true);
    ldg4f(bhB, bh + 16 + c4, true);

    u32 rhF[2][8], rlF[2][8];
    #pragma unroll
    for (int mt = 0; mt < 2; mt++) {
        #pragma unroll
        for (int grp = 0; grp < 2; grp++) {
            const float* bzv = grp ? bzB : bzA;
            const float* bhv = grp ? bhB : bhA;
            #pragma unroll
            for (int rh = 0; rh < 2; rh++) {
                const float* hX = grp ? hB[mt][rh] : hA[mt][rh];
                float hn[4];
                #pragma unroll
                for (int q = 0; q < 4; q++) {
                    int nt4 = grp * 2 + (q >> 1);
                    int ri  = rh * 2 + (q & 1);
                    float zg = sigm(c1[mt][nt4][ri] + bzv[q]);
                    float ht = tanh_hw(cc[mt][nt4][ri] + bhv[q]);
                    hn[q] = fmaf(zg, hX[q] - ht, ht);
                }
                if (vv[mt][rh])
                    *reinterpret_cast<float4*>(hnew + (size_t)rr[mt][rh] * HID + grp * 16 + c4) =
                        make_float4(hn[0], hn[1], hn[2], hn[3]);
                int i0 = grp * 4 + rh;
                int i1 = grp * 4 + 2 + rh;
                splitf2(fmaxf(hn[0], 0.0f), fmaxf(hn[1], 0.0f), rhF[mt][i0], rlF[mt][i0]);
                splitf2(fmaxf(hn[2], 0.0f), fmaxf(hn[3], 0.0f), rhF[mt][i1], rlF[mt][i1]);
            }
        }
    }

    /* ---- GEMM3: out[32x8] = relu(hn) @ w_lin ---- */
    float co[2][4];
    #pragma unroll
    for (int mt = 0; mt < 2; mt++)
        #pragma unroll
        for (int i = 0; i < 4; i++) co[mt][i] = 0.0f;

    #pragma unroll
    for (int kt = 0; kt < 2; kt++) {
        uint4 B = __ldg(&gBl[kt * 32 + lane]);
        #pragma unroll
        for (int mt = 0; mt < 2; mt++)
            mma3(co[mt], &rhF[mt][kt * 4], &rlF[mt][kt * 4], B);
    }

    float2 blv = *reinterpret_cast<const float2*>(bl + c2);
    #pragma unroll
    for (int mt = 0; mt < 2; mt++) {
        if (vv[mt][0])
            *reinterpret_cast<float2*>(out + (size_t)rr[mt][0] * OUT_DIM + c2) =
                make_float2(co[mt][0] + blv.x, co[mt][1] + blv.y);
        if (vv[mt][1])
            *reinterpret_cast<float2*>(out + (size_t)rr[mt][1] * OUT_DIM + c2) =
                make_float2(co[mt][2] + blv.x, co[mt][3] + blv.y);
    }
}

extern "C" void kernel_launch(void* const* d_in, const int* in_sizes, int n_in,
                              void* d_out, int out_size) {
    const float* x  = (const float*)d_in[0];
    const float* h  = (const float*)d_in[3];
    const float* wz = (const float*)d_in[4];
    const float* bz = (const float*)d_in[5];
    const float* wr = (const float*)d_in[6];
    const float* br = (const float*)d_in[7];
    const float* wh = (const float*)d_in[8];
    const float* bh = (const float*)d_in[9];
    const float* wl = (const float*)d_in[10];
    const float* bl = (const float*)d_in[11];

    int N = in_sizes[0] / IN_DIM;
    float* out  = (float*)d_out;
    float* hnew = out + (size_t)N * OUT_DIM;

    rgcn_prep<<<5, 256>>>(wz, wr, wh, wl);

    int grid = (N + TILE_M - 1) / TILE_M;
    rgcn_mma_kernel<<<grid, TPB>>>(x, h, bz, br, bh, bl, out, hnew, N);
}

// round 8
// speedup vs baseline: 4.0804x; 1.0964x over previous
#include <cuda_runtime.h>
#include <cstdint>

typedef uint32_t u32;

#define IN_DIM 16
#define HID 32
#define OUT_DIM 8
#define TPB 128
#define TILE_M 128   /* 4 warps x 32 rows (mt=2) */

/* ---- fragment-ordered tf32 weight tables ----
   uint4 = {b0_even, b1_even, b0_odd, b1_odd} for a k-tile pair.
   k-perm: pair u, slot j in 0..3  ->  logical k = 16u + 4*ctg + j
   n-perm (32-col groups): slot (nt4, g) -> n = (nt4>>1)*16 + (nt4&1)*2 + (g>>1)*4 + (g&1) */
__device__ uint4 gB1[768];   /* z|r: 3 pairs x 8 nt x 32 lanes */
__device__ uint4 gBh[384];   /* h~ : 3 pairs x 4 nt x 32 lanes */
__device__ uint4 gBl[64];    /* lin: 2 pairs x 1 nt x 32 lanes */

/* ---------------- helpers ---------------- */
__device__ __forceinline__ u32 tf32c(float f) {
    u32 r;
    asm("cvt.rn.tf32.f32 %0, %1;" : "=r"(r) : "f"(f));
    return r;
}
__device__ __forceinline__ float tanh_hw(float x) {
    float y;
    asm("tanh.approx.f32 %0, %1;" : "=f"(y) : "f"(x));
    return y;
}
__device__ __forceinline__ float sigm(float v) {
    return fmaf(tanh_hw(0.5f * v), 0.5f, 0.5f);
}
__device__ __forceinline__ void ldg4f(float* d, const float* p, bool v) {
    float4 t = make_float4(0.0f, 0.0f, 0.0f, 0.0f);
    if (v) t = *reinterpret_cast<const float4*>(p);
    d[0] = t.x; d[1] = t.y; d[2] = t.z; d[3] = t.w;
}
__device__ __forceinline__ void mma1688(float c[4], const u32 a[4], u32 b0, u32 b1) {
    asm volatile(
        "mma.sync.aligned.m16n8k8.row.col.f32.tf32.tf32.f32 "
        "{%0,%1,%2,%3}, {%4,%5,%6,%7}, {%8,%9}, {%0,%1,%2,%3};"
        : "+f"(c[0]), "+f"(c[1]), "+f"(c[2]), "+f"(c[3])
        : "r"(a[0]), "r"(a[1]), "r"(a[2]), "r"(a[3]), "r"(b0), "r"(b1));
}
__device__ __forceinline__ void mma_pair(float c[4], const u32 ae[4], const u32 ao[4], uint4 B) {
    mma1688(c, ae, B.x, B.y);
    mma1688(c, ao, B.z, B.w);
}
/* rows v0 (gid), v1 (gid+8): 4 contiguous logical k each -> even/odd tile frags */
__device__ __forceinline__ void packA(const float* v0, const float* v1, u32 ae[4], u32 ao[4]) {
    ae[0] = tf32c(v0[0]); ae[1] = tf32c(v1[0]); ae[2] = tf32c(v0[1]); ae[3] = tf32c(v1[1]);
    ao[0] = tf32c(v0[2]); ao[1] = tf32c(v1[2]); ao[2] = tf32c(v0[3]); ao[3] = tf32c(v1[3]);
}

/* ====== prep: fold w0+w1, apply k/n perms, emit tf32 fragments ====== */
__global__ void rgcn_prep(const float* __restrict__ wz, const float* __restrict__ wr,
                          const float* __restrict__ wh, const float* __restrict__ wl) {
    int idx = blockIdx.x * blockDim.x + threadIdx.x;
    if (idx >= 38 * 32) return;
    int lane = idx & 31, fid = idx >> 5;
    int gid = lane >> 2, ctg = lane & 3;

    u32 o[4];
    if (fid < 24) {                 /* B1: z (nt 0..3) | r (nt 4..7) */
        int u = fid >> 3, nt = fid & 7, nt4 = nt & 3;
        int L = ((nt4 >> 1) << 4) + ((nt4 & 1) << 1) + ((gid >> 1) << 2) + (gid & 1);
        #pragma unroll
        for (int j = 0; j < 4; j++) {
            int k = u * 16 + ctg * 4 + j;
            float val = (nt < 4) ? wz[k * 32 + L] + wz[1536 + k * 32 + L]
                                 : wr[k * 32 + L] + wr[1536 + k * 32 + L];
            o[j] = tf32c(val);
        }
        gB1[fid * 32 + lane] = make_uint4(o[0], o[1], o[2], o[3]);
    } else if (fid < 36) {          /* B_h */
        int f = fid - 24;
        int u = f >> 2, nt = f & 3;
        int L = ((nt >> 1) << 4) + ((nt & 1) << 1) + ((gid >> 1) << 2) + (gid & 1);
        #pragma unroll
        for (int j = 0; j < 4; j++) {
            int k = u * 16 + ctg * 4 + j;
            o[j] = tf32c(wh[k * 32 + L] + wh[1536 + k * 32 + L]);
        }
        gBh[f * 32 + lane] = make_uint4(o[0], o[1], o[2], o[3]);
    } else {                        /* B_lin (identity n) */
        int u = fid - 36;
        #pragma unroll
        for (int j = 0; j < 4; j++) {
            int k = u * 16 + ctg * 4 + j;
            o[j] = tf32c(wl[k * 8 + gid]);
        }
        gBl[u * 32 + lane] = make_uint4(o[0], o[1], o[2], o[3]);
    }
}

/* ====== main fused kernel: mt=2, zero smem, tf32 single-product ====== */
__global__ void __launch_bounds__(TPB, 3) rgcn_mma_kernel(
    const float* __restrict__ x, const float* __restrict__ h,
    const float* __restrict__ bz, const float* __restrict__ br,
    const float* __restrict__ bh, const float* __restrict__ bl,
    float* __restrict__ out, float* __restrict__ hnew, int N)
{
    const int tid  = threadIdx.x;
    const int lane = tid & 31;
    const int warp = tid >> 5;
    const int gid  = lane >> 2, ctg = lane & 3;
    const int c4   = 4 * ctg, c2 = 2 * ctg;
    const int rowBase = blockIdx.x * TILE_M + warp * 32;

    int  rr[2][2];
    bool vv[2][2];
    #pragma unroll
    for (int mt = 0; mt < 2; mt++)
        #pragma unroll
        for (int rh = 0; rh < 2; rh++) {
            rr[mt][rh] = rowBase + mt * 16 + gid + rh * 8;
            vv[mt][rh] = rr[mt][rh] < N;
        }

    /* ---- vectorized loads at permuted fragment coordinates ---- */
    float xv[2][2][4], hA[2][2][4], hB[2][2][4];
    #pragma unroll
    for (int mt = 0; mt < 2; mt++)
        #pragma unroll
        for (int rh = 0; rh < 2; rh++) {
            ldg4f(xv[mt][rh], x + (size_t)rr[mt][rh] * IN_DIM + c4,    vv[mt][rh]);
            ldg4f(hA[mt][rh], h + (size_t)rr[mt][rh] * HID + c4,      vv[mt][rh]);
            ldg4f(hB[mt][rh], h + (size_t)rr[mt][rh] * HID + 16 + c4, vv[mt][rh]);
        }

    /* x fragments (pair u=0), reused by GEMM1 and GEMM2 */
    u32 xae[2][4], xao[2][4];
    #pragma unroll
    for (int mt = 0; mt < 2; mt++) packA(xv[mt][0], xv[mt][1], xae[mt], xao[mt]);

    /* ---- GEMM1: C1[32x64] = [x|h] @ B_zr (fused z|r) ---- */
    float c1[2][8][4];
    #pragma unroll
    for (int mt = 0; mt < 2; mt++)
        #pragma unroll
        for (int nt = 0; nt < 8; nt++)
            #pragma unroll
            for (int i = 0; i < 4; i++) c1[mt][nt][i] = 0.0f;

    #pragma unroll
    for (int u = 0; u < 3; u++) {
        u32 ae[2][4], ao[2][4];
        #pragma unroll
        for (int mt = 0; mt < 2; mt++) {
            if (u == 0) {
                #pragma unroll
                for (int j = 0; j < 4; j++) { ae[mt][j] = xae[mt][j]; ao[mt][j] = xao[mt][j]; }
            } else if (u == 1) packA(hA[mt][0], hA[mt][1], ae[mt], ao[mt]);
            else               packA(hB[mt][0], hB[mt][1], ae[mt], ao[mt]);
        }
        #pragma unroll
        for (int nt = 0; nt < 8; nt++) {
            uint4 B = __ldg(&gB1[(u * 8 + nt) * 32 + lane]);
            mma_pair(c1[0][nt], ae[0], ao[0], B);
            mma_pair(c1[1][nt], ae[1], ao[1], B);
        }
    }

    /* ---- epilogue 1: a2 = h * sigmoid(r+br); pack into GEMM2 A-frags ---- */
    float brA[4], brB[4];
    ldg4f(brA, br + c4, true);
    ldg4f(brB, br + 16 + c4, true);

    u32 a2e[2][2][4], a2o[2][2][4];   /* [mt][grp] -> pair u=grp+1 */
    #pragma unroll
    for (int mt = 0; mt < 2; mt++)
        #pragma unroll
        for (int grp = 0; grp < 2; grp++) {
            const float* brv = grp ? brB : brA;
            float vals[2][4];
            #pragma unroll
            for (int rh = 0; rh < 2; rh++) {
                const float* hX = grp ? hB[mt][rh] : hA[mt][rh];
                #pragma unroll
                for (int q = 0; q < 4; q++) {
                    int nt = 4 + grp * 2 + (q >> 1);
                    int ri = rh * 2 + (q & 1);
                    vals[rh][q] = hX[q] * sigm(c1[mt][nt][ri] + brv[q]);
                }
            }
            packA(vals[0], vals[1], a2e[mt][grp], a2o[mt][grp]);
        }

    /* ---- GEMM2: CC[32x32] = [x | a2] @ B_h ---- */
    float cc[2][4][4];
    #pragma unroll
    for (int mt = 0; mt < 2; mt++)
        #pragma unroll
        for (int nt = 0; nt < 4; nt++)
            #pragma unroll
            for (int i = 0; i < 4; i++) cc[mt][nt][i] = 0.0f;

    #pragma unroll
    for (int u = 0; u < 3; u++) {
        #pragma unroll
        for (int nt = 0; nt < 4; nt++) {
            uint4 B = __ldg(&gBh[(u * 4 + nt) * 32 + lane]);
            #pragma unroll
            for (int mt = 0; mt < 2; mt++) {
                const u32* ae = (u == 0) ? xae[mt] : a2e[mt][u - 1];
                const u32* ao = (u == 0) ? xao[mt] : a2o[mt][u - 1];
                mma_pair(cc[mt][nt], ae, ao, B);
            }
        }
    }

    /* ---- epilogue 2: hn = h~ + z*(h - h~); store; pack relu(hn) ---- */
    float bzA[4], bzB[4], bhA[4], bhB[4];
    ldg4f(bzA, bz + c4, true);
    ldg4f(bzB, bz + 16 + c4, true);
    ldg4f(bhA, bh + c4, true);
    ldg4f(bhB, bh + 16 + c4, true);

    u32 re[2][2][4], ro[2][2][4];
    #pragma unroll
    for (int mt = 0; mt < 2; mt++)
        #pragma unroll
        for (int grp = 0; grp < 2; grp++) {
            const float* bzv = grp ? bzB : bzA;
            const float* bhv = grp ? bhB : bhA;
            float rel[2][4];
            #pragma unroll
            for (int rh = 0; rh < 2; rh++) {
                const float* hX = grp ? hB[mt][rh] : hA[mt][rh];
                float hn[4];
                #pragma unroll
                for (int q = 0; q < 4; q++) {
                    int nt = grp * 2 + (q >> 1);
                    int ri = rh * 2 + (q & 1);
                    float zg = sigm(c1[mt][nt][ri] + bzv[q]);
                    float ht = tanh_hw(cc[mt][nt][ri] + bhv[q]);
                    hn[q] = fmaf(zg, hX[q] - ht, ht);
                    rel[rh][q] = fmaxf(hn[q], 0.0f);
                }
                if (vv[mt][rh])
                    *reinterpret_cast<float4*>(hnew + (size_t)rr[mt][rh] * HID + grp * 16 + c4) =
                        make_float4(hn[0], hn[1], hn[2], hn[3]);
            }
            packA(rel[0], rel[1], re[mt][grp], ro[mt][grp]);
        }

    /* ---- GEMM3: out[32x8] = relu(hn) @ w_lin ---- */
    float co[2][4];
    #pragma unroll
    for (int mt = 0; mt < 2; mt++)
        #pragma unroll
        for (int i = 0; i < 4; i++) co[mt][i] = 0.0f;

    #pragma unroll
    for (int u = 0; u < 2; u++) {
        uint4 B = __ldg(&gBl[u * 32 + lane]);
        #pragma unroll
        for (int mt = 0; mt < 2; mt++)
            mma_pair(co[mt], re[mt][u], ro[mt][u], B);
    }

    float2 blv = *reinterpret_cast<const float2*>(bl + c2);
    #pragma unroll
    for (int mt = 0; mt < 2; mt++) {
        if (vv[mt][0])
            *reinterpret_cast<float2*>(out + (size_t)rr[mt][0] * OUT_DIM + c2) =
                make_float2(co[mt][0] + blv.x, co[mt][1] + blv.y);
        if (vv[mt][1])
            *reinterpret_cast<float2*>(out + (size_t)rr[mt][1] * OUT_DIM + c2) =
                make_float2(co[mt][2] + blv.x, co[mt][3] + blv.y);
    }
}

extern "C" void kernel_launch(void* const* d_in, const int* in_sizes, int n_in,
                              void* d_out, int out_size) {
    const float* x  = (const float*)d_in[0];
    const float* h  = (const float*)d_in[3];
    const float* wz = (const float*)d_in[4];
    const float* bz = (const float*)d_in[5];
    const float* wr = (const float*)d_in[6];
    const float* br = (const float*)d_in[7];
    const float* wh = (const float*)d_in[8];
    const float* bh = (const float*)d_in[9];
    const float* wl = (const float*)d_in[10];
    const float* bl = (const float*)d_in[11];

    int N = in_sizes[0] / IN_DIM;
    float* out  = (float*)d_out;
    float* hnew = out + (size_t)N * OUT_DIM;

    rgcn_prep<<<5, 256>>>(wz, wr, wh, wl);

    int grid = (N + TILE_M - 1) / TILE_M;
    rgcn_mma_kernel<<<grid, TPB>>>(x, h, bz, br, bh, bl, out, hnew, N);
}